// round 2
// baseline (speedup 1.0000x reference)
#include <cuda_runtime.h>
#include <math.h>
#include <stdint.h>
#include <stddef.h>

// Problem dims (fixed by the dataset)
#define NS   4096      // batch
#define TS   64        // timesteps
#define FI   32        // input features
#define HD   128       // hidden
#define GD   384       // 3*H
#define NK   20        // top-k
#define SLOPE_F 0.2f

// ---------------- scratch (device globals; no runtime allocation) ----------
__device__ float d_gi[(size_t)NS * TS * GD];     // gi0, then reused as gi1 (402MB)
__device__ float d_h0[(size_t)NS * TS * HD];     // layer0 hidden sequence (134MB)
__device__ float d_g  [NS * HD];
__device__ float d_gn [NS * HD];
__device__ float d_sim[(size_t)NS * NS];         // sim, then S, then attn (64MB)
__device__ int   d_tidx[NS * NK];
__device__ float d_tval[NS * NK];
__device__ float d_colsum[NS];
__device__ float d_colZ[NS];
__device__ float d_valid[NS];
__device__ float d_concept[NS * HD];
__device__ float d_cf [NS * HD];
__device__ float d_cfn[NS * HD];
__device__ float d_hsb[NS * HD];
__device__ float d_t1 [NS * HD];
__device__ float d_t2 [NS * HD];
__device__ float d_t3 [NS * HD];
__device__ float d_t4 [NS * HD];

// ---------------- generic fp32 GEMM:  C = act(A @ op(B) + bias) * rowscale --
// A: [M,K] row-major. TRANSB: B is [N,K] (use B[n,k]); else B is [K,N].
// Tile 64x64x16, 256 threads, 4x4 microtile.
template<bool TRANSB, bool ACT>
__global__ __launch_bounds__(256) void k_gemm(
    const float* __restrict__ A, const float* __restrict__ B,
    const float* __restrict__ bias, const float* __restrict__ rs,
    float* __restrict__ C, int M, int N, int K)
{
    __shared__ float As[16][68];
    __shared__ float Bs[16][68];
    const int bm = blockIdx.y * 64, bn = blockIdx.x * 64;
    const int tid = threadIdx.x;
    const int tx = tid & 15, ty = tid >> 4;
    const int la_m = tid >> 2, la_k = (tid & 3) * 4;   // A / B-trans loader
    const int lb_k = tid >> 4, lb_n = (tid & 15) * 4;  // B non-trans loader
    float acc[4][4] = {};

    for (int k0 = 0; k0 < K; k0 += 16) {
        float4 av = *(const float4*)(A + (size_t)(bm + la_m) * K + k0 + la_k);
        As[la_k + 0][la_m] = av.x; As[la_k + 1][la_m] = av.y;
        As[la_k + 2][la_m] = av.z; As[la_k + 3][la_m] = av.w;
        if (TRANSB) {
            float4 bv = *(const float4*)(B + (size_t)(bn + la_m) * K + k0 + la_k);
            Bs[la_k + 0][la_m] = bv.x; Bs[la_k + 1][la_m] = bv.y;
            Bs[la_k + 2][la_m] = bv.z; Bs[la_k + 3][la_m] = bv.w;
        } else {
            float4 bv = *(const float4*)(B + (size_t)(k0 + lb_k) * N + bn + lb_n);
            *(float4*)&Bs[lb_k][lb_n] = bv;
        }
        __syncthreads();
        #pragma unroll
        for (int kk = 0; kk < 16; kk++) {
            float4 a = *(const float4*)&As[kk][ty * 4];
            float4 b = *(const float4*)&Bs[kk][tx * 4];
            acc[0][0] = fmaf(a.x, b.x, acc[0][0]); acc[0][1] = fmaf(a.x, b.y, acc[0][1]);
            acc[0][2] = fmaf(a.x, b.z, acc[0][2]); acc[0][3] = fmaf(a.x, b.w, acc[0][3]);
            acc[1][0] = fmaf(a.y, b.x, acc[1][0]); acc[1][1] = fmaf(a.y, b.y, acc[1][1]);
            acc[1][2] = fmaf(a.y, b.z, acc[1][2]); acc[1][3] = fmaf(a.y, b.w, acc[1][3]);
            acc[2][0] = fmaf(a.z, b.x, acc[2][0]); acc[2][1] = fmaf(a.z, b.y, acc[2][1]);
            acc[2][2] = fmaf(a.z, b.z, acc[2][2]); acc[2][3] = fmaf(a.z, b.w, acc[2][3]);
            acc[3][0] = fmaf(a.w, b.x, acc[3][0]); acc[3][1] = fmaf(a.w, b.y, acc[3][1]);
            acc[3][2] = fmaf(a.w, b.z, acc[3][2]); acc[3][3] = fmaf(a.w, b.w, acc[3][3]);
        }
        __syncthreads();
    }
    #pragma unroll
    for (int i = 0; i < 4; i++) {
        int cm = bm + ty * 4 + i;
        float rsv = rs ? rs[cm] : 1.f;
        float vb[4];
        #pragma unroll
        for (int j = 0; j < 4; j++) {
            float v = acc[i][j];
            if (bias) v += bias[bn + tx * 4 + j];
            if (ACT)  v = v > 0.f ? v : SLOPE_F * v;
            vb[j] = v * rsv;
        }
        *(float4*)(C + (size_t)cm * N + bn + tx * 4) =
            make_float4(vb[0], vb[1], vb[2], vb[3]);
    }
}

// ---------------- persistent GRU recurrent kernel ---------------------------
// One CTA per 32 batch rows. 384 threads; thread o owns Whh row o in registers.
// gi = precomputed x@Wih^T + bih, laid out [n, t, 384].
template<bool WRITE_SEQ>
__global__ __launch_bounds__(384, 1) void k_gru(
    const float* __restrict__ gi, const float* __restrict__ Whh,
    const float* __restrict__ bhh, float* __restrict__ hout)
{
    extern __shared__ float sm[];
    float* h_sh  = sm;            // 32*128
    float* gh_sh = sm + 32 * HD;  // 32*384
    const int o = threadIdx.x;
    const int base = blockIdx.x * 32;

    float w[128];
    const float4* wg = (const float4*)(Whh + (size_t)o * HD);
    #pragma unroll
    for (int q = 0; q < 32; q++) {
        float4 tv = wg[q];
        w[4*q] = tv.x; w[4*q+1] = tv.y; w[4*q+2] = tv.z; w[4*q+3] = tv.w;
    }
    float bo = bhh[o];
    for (int idx = o; idx < 32 * HD; idx += GD) h_sh[idx] = 0.f;
    __syncthreads();

    for (int t = 0; t < TS; t++) {
        // gh[r,o] = h[r,:] . Whh[o,:]
        for (int r = 0; r < 32; r++) {
            const float4* h4 = (const float4*)(h_sh + r * HD);
            float acc = 0.f;
            #pragma unroll
            for (int q = 0; q < 32; q++) {
                float4 hv = h4[q];
                acc = fmaf(hv.x, w[4*q],   acc);
                acc = fmaf(hv.y, w[4*q+1], acc);
                acc = fmaf(hv.z, w[4*q+2], acc);
                acc = fmaf(hv.w, w[4*q+3], acc);
            }
            gh_sh[r * GD + o] = acc + bo;
        }
        __syncthreads();
        // gate update
        for (int idx = o; idx < 32 * HD; idx += GD) {
            int r = idx >> 7, j = idx & 127;
            size_t gib = ((size_t)(base + r) * TS + t) * GD;
            float gir = gi[gib + j];
            float giz = gi[gib + j + 128];
            float gin = gi[gib + j + 256];
            float ghr = gh_sh[r * GD + j];
            float ghz = gh_sh[r * GD + j + 128];
            float ghn = gh_sh[r * GD + j + 256];
            float rg = 1.f / (1.f + expf(-(gir + ghr)));
            float zg = 1.f / (1.f + expf(-(giz + ghz)));
            float ng = tanhf(gin + rg * ghn);
            float hprev = h_sh[idx];
            float hn = (1.f - zg) * ng + zg * hprev;
            h_sh[idx] = hn;
            if (WRITE_SEQ)
                hout[((size_t)(base + r) * TS + t) * HD + j] = hn;
            else if (t == TS - 1)
                hout[(size_t)(base + r) * HD + j] = hn;
        }
        __syncthreads();
    }
}

// ---------------- small helpers --------------------------------------------
__global__ void k_zero(float* p, int n) {
    int i = blockIdx.x * blockDim.x + threadIdx.x;
    if (i < n) p[i] = 0.f;
}

// row L2-normalize (128 floats/row), zero-norm rows -> zero
__global__ void k_rownorm(const float* __restrict__ src, float* __restrict__ dst) {
    int row = blockIdx.x * 8 + (threadIdx.x >> 5);
    int lane = threadIdx.x & 31;
    const float4* s4 = (const float4*)(src + (size_t)row * HD);
    float4 v = s4[lane];
    float ss = v.x*v.x + v.y*v.y + v.z*v.z + v.w*v.w;
    #pragma unroll
    for (int off = 16; off; off >>= 1) ss += __shfl_xor_sync(0xffffffffu, ss, off);
    float n = sqrtf(ss);
    float inv = (n > 0.f) ? 1.f / n : 0.f;
    ((float4*)(dst + (size_t)row * HD))[lane] =
        make_float4(v.x*inv, v.y*inv, v.z*inv, v.w*inv);
}

// top-K=20 per row of |sim| (diag excluded), jax-stable ties (lowest index).
__global__ __launch_bounds__(256) void k_topk(
    const float* __restrict__ sim, int* __restrict__ tidx,
    float* __restrict__ tval, float* __restrict__ colsum)
{
    int i = blockIdx.x;
    __shared__ float sabs[NS];
    __shared__ float wv[8];
    __shared__ int   wi[8];
    const float* row = sim + (size_t)i * NS;
    for (int c = threadIdx.x; c < NS; c += 256)
        sabs[c] = (c == i) ? -1.f : fabsf(row[c]);
    __syncthreads();
    for (int k = 0; k < NK; k++) {
        float bv = -2.f; int bi = 0;
        for (int c = threadIdx.x; c < NS; c += 256) {
            float v = sabs[c];
            if (v > bv) { bv = v; bi = c; }
        }
        #pragma unroll
        for (int off = 16; off; off >>= 1) {
            float ov = __shfl_down_sync(0xffffffffu, bv, off);
            int   oi = __shfl_down_sync(0xffffffffu, bi, off);
            if (ov > bv || (ov == bv && oi < bi)) { bv = ov; bi = oi; }
        }
        if ((threadIdx.x & 31) == 0) { wv[threadIdx.x >> 5] = bv; wi[threadIdx.x >> 5] = bi; }
        __syncthreads();
        if (threadIdx.x == 0) {
            for (int wd = 1; wd < 8; wd++)
                if (wv[wd] > bv || (wv[wd] == bv && wi[wd] < bi)) { bv = wv[wd]; bi = wi[wd]; }
            tidx[i * NK + k] = bi;
            float sv = row[bi];
            tval[i * NK + k] = sv;
            atomicAdd(&colsum[bi], sv);
            sabs[bi] = -2.f;
        }
        __syncthreads();
    }
}

// concept[c,:] += tval * g[i,:]  for each selected (i,c)
__global__ void k_scatter(const int* __restrict__ tidx, const float* __restrict__ tval,
                          const float* __restrict__ g, float* __restrict__ concept)
{
    int i = blockIdx.x, d = threadIdx.x;  // 128 threads
    float gv = g[(size_t)i * HD + d];
    #pragma unroll
    for (int k = 0; k < NK; k++) {
        int c = __ldg(&tidx[i * NK + k]);
        float v = __ldg(&tval[i * NK + k]);
        atomicAdd(&concept[(size_t)c * HD + d], v * gv);
    }
}

// add diag term where colsum!=0; compute valid[j] = (rowsum(concept[j]) != 0)
__global__ void k_diag_valid(const float* __restrict__ colsum, const float* __restrict__ sim,
                             const float* __restrict__ g, float* __restrict__ concept,
                             float* __restrict__ valid)
{
    int j = blockIdx.x, t = threadIdx.x;  // 128 threads
    float cs = colsum[j];
    float v = concept[(size_t)j * HD + t];
    if (cs != 0.f) {
        float dg = sim[(size_t)j * NS + j];
        v += dg * g[(size_t)j * HD + t];
        concept[(size_t)j * HD + t] = v;
    }
    float s = v;
    #pragma unroll
    for (int off = 16; off; off >>= 1) s += __shfl_xor_sync(0xffffffffu, s, off);
    __shared__ float ws[4];
    if ((t & 31) == 0) ws[t >> 5] = s;
    __syncthreads();
    if (t == 0) {
        float tot = ws[0] + ws[1] + ws[2] + ws[3];
        valid[j] = (tot != 0.f) ? 1.f : 0.f;
    }
}

// column sums of exp(S) (values bounded by 1, no max-shift needed)
__global__ void k_colz(const float* __restrict__ S, float* __restrict__ colZ) {
    int col = blockIdx.x * 128 + threadIdx.x;
    int r0 = blockIdx.y * 128;
    float s = 0.f;
    for (int r = r0; r < r0 + 128; r++) s += expf(S[(size_t)r * NS + col]);
    atomicAdd(&colZ[col], s);
}

// attn = exp(S) / colZ  (in place)
__global__ void k_scale(float* __restrict__ S, const float* __restrict__ colZ) {
    size_t q = (size_t)blockIdx.x * blockDim.x + threadIdx.x;  // float4 index
    size_t b = q * 4;
    float4 v = *(float4*)(S + b);
    int c = (int)(b & (NS - 1));
    float4 z = *(const float4*)(colZ + c);
    v.x = expf(v.x) / z.x; v.y = expf(v.y) / z.y;
    v.z = expf(v.z) / z.z; v.w = expf(v.w) / z.w;
    *(float4*)(S + b) = v;
}

__global__ void k_sub(const float* __restrict__ a, const float* __restrict__ b,
                      float* __restrict__ c) {
    size_t q = (size_t)blockIdx.x * blockDim.x + threadIdx.x;
    float4 av = *(const float4*)(a + q * 4);
    float4 bv = *(const float4*)(b + q * 4);
    *(float4*)(c + q * 4) = make_float4(av.x-bv.x, av.y-bv.y, av.z-bv.z, av.w-bv.w);
}

// pred[i] = (fore[i]+indi[i]) . W_out + b_out
__global__ void k_final(const float* __restrict__ fore, const float* __restrict__ indi,
                        const float* __restrict__ Wout, const float* __restrict__ bout,
                        float* __restrict__ out)
{
    int row = blockIdx.x * 8 + (threadIdx.x >> 5);
    int lane = threadIdx.x & 31;
    float4 a = ((const float4*)(fore + (size_t)row * HD))[lane];
    float4 b = ((const float4*)(indi + (size_t)row * HD))[lane];
    float4 w = ((const float4*)Wout)[lane];
    float s = (a.x+b.x)*w.x + (a.y+b.y)*w.y + (a.z+b.z)*w.z + (a.w+b.w)*w.w;
    #pragma unroll
    for (int off = 16; off; off >>= 1) s += __shfl_xor_sync(0xffffffffu, s, off);
    if (lane == 0) out[row] = s + bout[0];
}

// ---------------- driver -----------------------------------------------------
extern "C" void kernel_launch(void* const* d_in, const int* in_sizes, int n_in,
                              void* d_out, int out_size)
{
    const float* x     = (const float*)d_in[0];
    const float* Wih0  = (const float*)d_in[1];
    const float* Whh0  = (const float*)d_in[2];
    const float* bih0  = (const float*)d_in[3];
    const float* bhh0  = (const float*)d_in[4];
    const float* Wih1  = (const float*)d_in[5];
    const float* Whh1  = (const float*)d_in[6];
    const float* bih1  = (const float*)d_in[7];
    const float* bhh1  = (const float*)d_in[8];
    const float* W_hc  = (const float*)d_in[9];
    const float* b_hc  = (const float*)d_in[10];
    const float* W_hs  = (const float*)d_in[11];
    const float* b_hs  = (const float*)d_in[12];
    const float* W_fore= (const float*)d_in[13];
    const float* b_fore= (const float*)d_in[14];
    const float* W_back= (const float*)d_in[15];
    const float* b_back= (const float*)d_in[16];
    const float* W_indi= (const float*)d_in[17];
    const float* b_indi= (const float*)d_in[18];
    const float* W_out = (const float*)d_in[19];
    const float* b_out = (const float*)d_in[20];
    float* out = (float*)d_out;

    float *gi, *h0, *g, *gn, *sim, *colsum, *colZ, *valid, *concept;
    float *cf, *cfn, *hs, *t1, *t2, *t3, *t4, *tval;
    int* tidx;
    cudaGetSymbolAddress((void**)&gi,      d_gi);
    cudaGetSymbolAddress((void**)&h0,      d_h0);
    cudaGetSymbolAddress((void**)&g,       d_g);
    cudaGetSymbolAddress((void**)&gn,      d_gn);
    cudaGetSymbolAddress((void**)&sim,     d_sim);
    cudaGetSymbolAddress((void**)&tidx,    d_tidx);
    cudaGetSymbolAddress((void**)&tval,    d_tval);
    cudaGetSymbolAddress((void**)&colsum,  d_colsum);
    cudaGetSymbolAddress((void**)&colZ,    d_colZ);
    cudaGetSymbolAddress((void**)&valid,   d_valid);
    cudaGetSymbolAddress((void**)&concept, d_concept);
    cudaGetSymbolAddress((void**)&cf,      d_cf);
    cudaGetSymbolAddress((void**)&cfn,     d_cfn);
    cudaGetSymbolAddress((void**)&hs,      d_hsb);
    cudaGetSymbolAddress((void**)&t1,      d_t1);
    cudaGetSymbolAddress((void**)&t2,      d_t2);
    cudaGetSymbolAddress((void**)&t3,      d_t3);
    cudaGetSymbolAddress((void**)&t4,      d_t4);

    cudaFuncSetAttribute((const void*)k_gru<true>,
                         cudaFuncAttributeMaxDynamicSharedMemorySize, 65536);
    cudaFuncSetAttribute((const void*)k_gru<false>,
                         cudaFuncAttributeMaxDynamicSharedMemorySize, 65536);

    const int MT = NS * TS;  // 262144

    // zero accumulators (consumed later)
    k_zero<<<(NS * HD + 255) / 256, 256>>>(concept, NS * HD);
    k_zero<<<(NS + 255) / 256, 256>>>(colsum, NS);
    k_zero<<<(NS + 255) / 256, 256>>>(colZ, NS);

    // gi0 = x @ Wih0^T + bih0   [262144, 384], K=32
    k_gemm<true, false><<<dim3(GD / 64, MT / 64), 256>>>(
        x, Wih0, bih0, nullptr, gi, MT, GD, FI);
    // GRU layer 0 (writes full sequence)
    k_gru<true><<<128, 384, 65536>>>(gi, Whh0, bhh0, h0);
    // gi1 = h0 @ Wih1^T + bih1   [262144, 384], K=128
    k_gemm<true, false><<<dim3(GD / 64, MT / 64), 256>>>(
        h0, Wih1, bih1, nullptr, gi, MT, GD, HD);
    // GRU layer 1 (writes final hidden only -> g)
    k_gru<false><<<128, 384, 65536>>>(gi, Whh1, bhh1, g);

    // normalized g, sim = gn @ gn^T
    k_rownorm<<<NS / 8, 256>>>(g, gn);
    k_gemm<true, false><<<dim3(NS / 64, NS / 64), 256>>>(
        gn, gn, nullptr, nullptr, sim, NS, NS, HD);

    // top-K selection + concept aggregation
    k_topk<<<NS, 256>>>(sim, tidx, tval, colsum);
    k_scatter<<<NS, 128>>>(tidx, tval, g, concept);
    k_diag_valid<<<NS, 128>>>(colsum, sim, g, concept, valid);

    // cf = lrelu(concept @ W_hc^T + b_hc) * valid
    k_gemm<true, true><<<dim3(HD / 64, NS / 64), 256>>>(
        concept, W_hc, b_hc, valid, cf, NS, HD, HD);
    k_rownorm<<<NS / 8, 256>>>(cf, cfn);

    // S = gn @ cfn^T ; attn = softmax over axis 0
    k_gemm<true, false><<<dim3(NS / 64, NS / 64), 256>>>(
        gn, cfn, nullptr, nullptr, sim, NS, NS, HD);
    k_colz<<<dim3(NS / 128, NS / 128), 128>>>(sim, colZ);
    k_scale<<<(int)(((size_t)NS * NS / 4) / 256), 256>>>(sim, colZ);

    // hs = lrelu((attn @ cf) @ W_hs^T + b_hs)
    k_gemm<false, false><<<dim3(HD / 64, NS / 64), 256>>>(
        sim, cf, nullptr, nullptr, t1, NS, HD, NS);
    k_gemm<true, true><<<dim3(HD / 64, NS / 64), 256>>>(
        t1, W_hs, b_hs, nullptr, hs, NS, HD, HD);

    // back / fore / indi / pred
    k_gemm<true, true><<<dim3(HD / 64, NS / 64), 256>>>(
        hs, W_back, b_back, nullptr, t1, NS, HD, HD);
    k_gemm<true, true><<<dim3(HD / 64, NS / 64), 256>>>(
        hs, W_fore, b_fore, nullptr, t2, NS, HD, HD);
    k_sub<<<(NS * HD / 4) / 256, 256>>>(g, t1, t3);
    k_gemm<true, true><<<dim3(HD / 64, NS / 64), 256>>>(
        t3, W_indi, b_indi, nullptr, t4, NS, HD, HD);
    k_final<<<NS / 8, 256>>>(t2, t4, W_out, b_out, out);
}

// round 3
// speedup vs baseline: 1.0661x; 1.0661x over previous
#include <cuda_runtime.h>
#include <math.h>
#include <stdint.h>
#include <stddef.h>

// Problem dims (fixed by the dataset)
#define NS   4096      // batch
#define TS   64        // timesteps
#define FI   32        // input features
#define HD   128       // hidden
#define GD   384       // 3*H
#define NK   20        // top-k
#define SLOPE_F 0.2f

// ---------------- scratch (device globals; no runtime allocation) ----------
__device__ float d_gi[(size_t)NS * TS * GD];     // gi0/gi1, later split-K scratch
__device__ float d_h0[(size_t)NS * TS * HD];     // layer0 hidden sequence
__device__ float d_g  [NS * HD];
__device__ float d_gn [NS * HD];
__device__ float d_sim[(size_t)NS * NS];         // sim, then S, then attn
__device__ int   d_tidx[NS * NK];
__device__ float d_tval[NS * NK];
__device__ float d_colsum[NS];
__device__ float d_colZ[NS];
__device__ float d_valid[NS];
__device__ float d_concept[NS * HD];
__device__ float d_cf [NS * HD];
__device__ float d_cfn[NS * HD];
__device__ float d_hsb[NS * HD];
__device__ float d_t1 [NS * HD];
__device__ float d_t2 [NS * HD];
__device__ float d_t3 [NS * HD];
__device__ float d_t4 [NS * HD];

// ---------------- fp32 GEMM: 128x64 tile, 256 thr, 8x4 micro ----------------
// A: [M,K] row-major. TRANSB: B is [N,K]; else B is [K,N].
// gridDim.z = number of K-splits; ksplit = K / gridDim.z (multiple of 16).
// When gridDim.z > 1: writes raw partials at C + z*M*N (bias/act applied later).
template<bool TRANSB, bool ACT>
__global__ __launch_bounds__(256) void k_gemm(
    const float* __restrict__ A, const float* __restrict__ B,
    const float* __restrict__ bias, const float* __restrict__ rs,
    float* __restrict__ C, int M, int N, int K, int ksplit)
{
    __shared__ float As[16][132];
    __shared__ float Bs[16][68];
    const int bm = blockIdx.y * 128, bn = blockIdx.x * 64;
    const int tid = threadIdx.x;
    const int kbase = blockIdx.z * ksplit;

    const int a_m = tid >> 1, a_k = (tid & 1) * 8;
    const int ty = tid >> 4, tx = tid & 15;
    const int m0 = ty * 8, n0 = tx * 4;

    float acc[8][4] = {};

    for (int k0 = kbase; k0 < kbase + ksplit; k0 += 16) {
        const float* Ap = A + (size_t)(bm + a_m) * K + k0 + a_k;
        float4 av0 = *(const float4*)(Ap);
        float4 av1 = *(const float4*)(Ap + 4);
        As[a_k + 0][a_m] = av0.x; As[a_k + 1][a_m] = av0.y;
        As[a_k + 2][a_m] = av0.z; As[a_k + 3][a_m] = av0.w;
        As[a_k + 4][a_m] = av1.x; As[a_k + 5][a_m] = av1.y;
        As[a_k + 6][a_m] = av1.z; As[a_k + 7][a_m] = av1.w;
        if (TRANSB) {
            const int b_n = tid >> 2, b_k = (tid & 3) * 4;
            float4 bv = *(const float4*)(B + (size_t)(bn + b_n) * K + k0 + b_k);
            Bs[b_k + 0][b_n] = bv.x; Bs[b_k + 1][b_n] = bv.y;
            Bs[b_k + 2][b_n] = bv.z; Bs[b_k + 3][b_n] = bv.w;
        } else {
            const int b_k = tid >> 4, b_n4 = (tid & 15) * 4;
            *(float4*)&Bs[b_k][b_n4] =
                *(const float4*)(B + (size_t)(k0 + b_k) * N + bn + b_n4);
        }
        __syncthreads();
        #pragma unroll
        for (int kk = 0; kk < 16; kk++) {
            float4 a0 = *(const float4*)&As[kk][m0];
            float4 a1 = *(const float4*)&As[kk][m0 + 4];
            float4 b  = *(const float4*)&Bs[kk][n0];
            float am[8] = {a0.x, a0.y, a0.z, a0.w, a1.x, a1.y, a1.z, a1.w};
            #pragma unroll
            for (int i = 0; i < 8; i++) {
                acc[i][0] = fmaf(am[i], b.x, acc[i][0]);
                acc[i][1] = fmaf(am[i], b.y, acc[i][1]);
                acc[i][2] = fmaf(am[i], b.z, acc[i][2]);
                acc[i][3] = fmaf(am[i], b.w, acc[i][3]);
            }
        }
        __syncthreads();
    }

    float* Cw = C + (size_t)blockIdx.z * ((size_t)M * N);
    #pragma unroll
    for (int i = 0; i < 8; i++) {
        int cm = bm + m0 + i;
        float rsv = rs ? rs[cm] : 1.f;
        float vb[4];
        #pragma unroll
        for (int j = 0; j < 4; j++) {
            float v = acc[i][j];
            if (bias) v += bias[bn + n0 + j];
            if (ACT)  v = v > 0.f ? v : SLOPE_F * v;
            vb[j] = v * rsv;
        }
        *(float4*)(Cw + (size_t)cm * N + bn + n0) =
            make_float4(vb[0], vb[1], vb[2], vb[3]);
    }
}

// reduce over split-K partial slices: C = sum_z P[z]; (no bias/act needed here)
__global__ void k_reduce(const float* __restrict__ P, float* __restrict__ C,
                         int nslice, int total4)
{
    int i = blockIdx.x * blockDim.x + threadIdx.x;
    if (i >= total4) return;
    size_t b = (size_t)i * 4;
    float4 s = make_float4(0.f, 0.f, 0.f, 0.f);
    for (int z = 0; z < nslice; z++) {
        float4 v = *(const float4*)(P + (size_t)z * total4 * 4 + b);
        s.x += v.x; s.y += v.y; s.z += v.z; s.w += v.w;
    }
    *(float4*)(C + b) = s;
}

// ---------------- persistent GRU recurrent kernel ---------------------------
// One CTA per 32 batch rows. 384 threads; thread o owns Whh row o in registers.
// 4 independent FFMA accumulation chains (2 rows x 2 partials) for ILP.
template<bool WRITE_SEQ>
__global__ __launch_bounds__(384, 1) void k_gru(
    const float* __restrict__ gi, const float* __restrict__ Whh,
    const float* __restrict__ bhh, float* __restrict__ hout)
{
    extern __shared__ float sm[];
    float* h_sh  = sm;            // 32*128
    float* gh_sh = sm + 32 * HD;  // 32*384
    const int o = threadIdx.x;
    const int base = blockIdx.x * 32;

    float4 w4[32];
    const float4* wg = (const float4*)(Whh + (size_t)o * HD);
    #pragma unroll
    for (int q = 0; q < 32; q++) w4[q] = wg[q];
    float bo = bhh[o];
    for (int idx = o; idx < 32 * HD; idx += GD) h_sh[idx] = 0.f;
    __syncthreads();

    for (int t = 0; t < TS; t++) {
        // gh[r,o] = h[r,:] . Whh[o,:]  — two rows per iter, 4 acc chains
        #pragma unroll 1
        for (int r = 0; r < 32; r += 2) {
            const float4* hA = (const float4*)(h_sh + r * HD);
            const float4* hB = hA + 32;
            float a0 = 0.f, a1 = 0.f, b0 = 0.f, b1 = 0.f;
            #pragma unroll
            for (int q = 0; q < 32; q += 2) {
                float4 xA0 = hA[q], xA1 = hA[q + 1];
                float4 xB0 = hB[q], xB1 = hB[q + 1];
                a0 = fmaf(xA0.x, w4[q].x, a0);
                a1 = fmaf(xA1.x, w4[q+1].x, a1);
                b0 = fmaf(xB0.x, w4[q].x, b0);
                b1 = fmaf(xB1.x, w4[q+1].x, b1);
                a0 = fmaf(xA0.y, w4[q].y, a0);
                a1 = fmaf(xA1.y, w4[q+1].y, a1);
                b0 = fmaf(xB0.y, w4[q].y, b0);
                b1 = fmaf(xB1.y, w4[q+1].y, b1);
                a0 = fmaf(xA0.z, w4[q].z, a0);
                a1 = fmaf(xA1.z, w4[q+1].z, a1);
                b0 = fmaf(xB0.z, w4[q].z, b0);
                b1 = fmaf(xB1.z, w4[q+1].z, b1);
                a0 = fmaf(xA0.w, w4[q].w, a0);
                a1 = fmaf(xA1.w, w4[q+1].w, a1);
                b0 = fmaf(xB0.w, w4[q].w, b0);
                b1 = fmaf(xB1.w, w4[q+1].w, b1);
            }
            gh_sh[r * GD + o]       = (a0 + a1) + bo;
            gh_sh[(r + 1) * GD + o] = (b0 + b1) + bo;
        }
        __syncthreads();
        // gate update
        for (int idx = o; idx < 32 * HD; idx += GD) {
            int r = idx >> 7, j = idx & 127;
            size_t gib = ((size_t)(base + r) * TS + t) * GD;
            float gir = gi[gib + j];
            float giz = gi[gib + j + 128];
            float gin = gi[gib + j + 256];
            float ghr = gh_sh[r * GD + j];
            float ghz = gh_sh[r * GD + j + 128];
            float ghn = gh_sh[r * GD + j + 256];
            float rg = 1.f / (1.f + expf(-(gir + ghr)));
            float zg = 1.f / (1.f + expf(-(giz + ghz)));
            float ng = tanhf(gin + rg * ghn);
            float hprev = h_sh[idx];
            float hn = (1.f - zg) * ng + zg * hprev;
            h_sh[idx] = hn;
            if (WRITE_SEQ)
                hout[((size_t)(base + r) * TS + t) * HD + j] = hn;
            else if (t == TS - 1)
                hout[(size_t)(base + r) * HD + j] = hn;
        }
        __syncthreads();
    }
}

// ---------------- small helpers --------------------------------------------
__global__ void k_zero(float* p, int n) {
    int i = blockIdx.x * blockDim.x + threadIdx.x;
    if (i < n) p[i] = 0.f;
}

// row L2-normalize (128 floats/row), zero-norm rows -> zero
__global__ void k_rownorm(const float* __restrict__ src, float* __restrict__ dst) {
    int row = blockIdx.x * 8 + (threadIdx.x >> 5);
    int lane = threadIdx.x & 31;
    const float4* s4 = (const float4*)(src + (size_t)row * HD);
    float4 v = s4[lane];
    float ss = v.x*v.x + v.y*v.y + v.z*v.z + v.w*v.w;
    #pragma unroll
    for (int off = 16; off; off >>= 1) ss += __shfl_xor_sync(0xffffffffu, ss, off);
    float n = sqrtf(ss);
    float inv = (n > 0.f) ? 1.f / n : 0.f;
    ((float4*)(dst + (size_t)row * HD))[lane] =
        make_float4(v.x*inv, v.y*inv, v.z*inv, v.w*inv);
}

// top-K=20 per row of |sim| (diag excluded), jax-stable ties (lowest index).
__global__ __launch_bounds__(256) void k_topk(
    const float* __restrict__ sim, int* __restrict__ tidx,
    float* __restrict__ tval, float* __restrict__ colsum)
{
    int i = blockIdx.x;
    __shared__ float sabs[NS];
    __shared__ float wv[8];
    __shared__ int   wi[8];
    const float* row = sim + (size_t)i * NS;
    for (int c = threadIdx.x; c < NS; c += 256)
        sabs[c] = (c == i) ? -1.f : fabsf(row[c]);
    __syncthreads();
    for (int k = 0; k < NK; k++) {
        float bv = -2.f; int bi = 0;
        for (int c = threadIdx.x; c < NS; c += 256) {
            float v = sabs[c];
            if (v > bv) { bv = v; bi = c; }
        }
        #pragma unroll
        for (int off = 16; off; off >>= 1) {
            float ov = __shfl_down_sync(0xffffffffu, bv, off);
            int   oi = __shfl_down_sync(0xffffffffu, bi, off);
            if (ov > bv || (ov == bv && oi < bi)) { bv = ov; bi = oi; }
        }
        if ((threadIdx.x & 31) == 0) { wv[threadIdx.x >> 5] = bv; wi[threadIdx.x >> 5] = bi; }
        __syncthreads();
        if (threadIdx.x == 0) {
            for (int wd = 1; wd < 8; wd++)
                if (wv[wd] > bv || (wv[wd] == bv && wi[wd] < bi)) { bv = wv[wd]; bi = wi[wd]; }
            tidx[i * NK + k] = bi;
            float sv = row[bi];
            tval[i * NK + k] = sv;
            atomicAdd(&colsum[bi], sv);
            sabs[bi] = -2.f;
        }
        __syncthreads();
    }
}

// concept[c,:] += tval * g[i,:]  for each selected (i,c)
__global__ void k_scatter(const int* __restrict__ tidx, const float* __restrict__ tval,
                          const float* __restrict__ g, float* __restrict__ concept)
{
    int i = blockIdx.x, d = threadIdx.x;  // 128 threads
    float gv = g[(size_t)i * HD + d];
    #pragma unroll
    for (int k = 0; k < NK; k++) {
        int c = __ldg(&tidx[i * NK + k]);
        float v = __ldg(&tval[i * NK + k]);
        atomicAdd(&concept[(size_t)c * HD + d], v * gv);
    }
}

// add diag term where colsum!=0; compute valid[j] = (rowsum(concept[j]) != 0)
__global__ void k_diag_valid(const float* __restrict__ colsum, const float* __restrict__ sim,
                             const float* __restrict__ g, float* __restrict__ concept,
                             float* __restrict__ valid)
{
    int j = blockIdx.x, t = threadIdx.x;  // 128 threads
    float cs = colsum[j];
    float v = concept[(size_t)j * HD + t];
    if (cs != 0.f) {
        float dg = sim[(size_t)j * NS + j];
        v += dg * g[(size_t)j * HD + t];
        concept[(size_t)j * HD + t] = v;
    }
    float s = v;
    #pragma unroll
    for (int off = 16; off; off >>= 1) s += __shfl_xor_sync(0xffffffffu, s, off);
    __shared__ float ws[4];
    if ((t & 31) == 0) ws[t >> 5] = s;
    __syncthreads();
    if (t == 0) {
        float tot = ws[0] + ws[1] + ws[2] + ws[3];
        valid[j] = (tot != 0.f) ? 1.f : 0.f;
    }
}

// column sums of exp(S) (values bounded by 1, no max-shift needed)
__global__ void k_colz(const float* __restrict__ S, float* __restrict__ colZ) {
    int col = blockIdx.x * 128 + threadIdx.x;
    int r0 = blockIdx.y * 128;
    float s = 0.f;
    for (int r = r0; r < r0 + 128; r++) s += expf(S[(size_t)r * NS + col]);
    atomicAdd(&colZ[col], s);
}

// attn = exp(S) / colZ  (in place)
__global__ void k_scale(float* __restrict__ S, const float* __restrict__ colZ) {
    size_t q = (size_t)blockIdx.x * blockDim.x + threadIdx.x;  // float4 index
    size_t b = q * 4;
    float4 v = *(float4*)(S + b);
    int c = (int)(b & (NS - 1));
    float4 z = *(const float4*)(colZ + c);
    v.x = expf(v.x) / z.x; v.y = expf(v.y) / z.y;
    v.z = expf(v.z) / z.z; v.w = expf(v.w) / z.w;
    *(float4*)(S + b) = v;
}

__global__ void k_sub(const float* __restrict__ a, const float* __restrict__ b,
                      float* __restrict__ c) {
    size_t q = (size_t)blockIdx.x * blockDim.x + threadIdx.x;
    float4 av = *(const float4*)(a + q * 4);
    float4 bv = *(const float4*)(b + q * 4);
    *(float4*)(c + q * 4) = make_float4(av.x-bv.x, av.y-bv.y, av.z-bv.z, av.w-bv.w);
}

// pred[i] = (fore[i]+indi[i]) . W_out + b_out
__global__ void k_final(const float* __restrict__ fore, const float* __restrict__ indi,
                        const float* __restrict__ Wout, const float* __restrict__ bout,
                        float* __restrict__ out)
{
    int row = blockIdx.x * 8 + (threadIdx.x >> 5);
    int lane = threadIdx.x & 31;
    float4 a = ((const float4*)(fore + (size_t)row * HD))[lane];
    float4 b = ((const float4*)(indi + (size_t)row * HD))[lane];
    float4 w = ((const float4*)Wout)[lane];
    float s = (a.x+b.x)*w.x + (a.y+b.y)*w.y + (a.z+b.z)*w.z + (a.w+b.w)*w.w;
    #pragma unroll
    for (int off = 16; off; off >>= 1) s += __shfl_xor_sync(0xffffffffu, s, off);
    if (lane == 0) out[row] = s + bout[0];
}

// ---------------- driver -----------------------------------------------------
extern "C" void kernel_launch(void* const* d_in, const int* in_sizes, int n_in,
                              void* d_out, int out_size)
{
    const float* x     = (const float*)d_in[0];
    const float* Wih0  = (const float*)d_in[1];
    const float* Whh0  = (const float*)d_in[2];
    const float* bih0  = (const float*)d_in[3];
    const float* bhh0  = (const float*)d_in[4];
    const float* Wih1  = (const float*)d_in[5];
    const float* Whh1  = (const float*)d_in[6];
    const float* bih1  = (const float*)d_in[7];
    const float* bhh1  = (const float*)d_in[8];
    const float* W_hc  = (const float*)d_in[9];
    const float* b_hc  = (const float*)d_in[10];
    const float* W_hs  = (const float*)d_in[11];
    const float* b_hs  = (const float*)d_in[12];
    const float* W_fore= (const float*)d_in[13];
    const float* b_fore= (const float*)d_in[14];
    const float* W_back= (const float*)d_in[15];
    const float* b_back= (const float*)d_in[16];
    const float* W_indi= (const float*)d_in[17];
    const float* b_indi= (const float*)d_in[18];
    const float* W_out = (const float*)d_in[19];
    const float* b_out = (const float*)d_in[20];
    float* out = (float*)d_out;

    float *gi, *h0, *g, *gn, *sim, *colsum, *colZ, *valid, *concept;
    float *cf, *cfn, *hs, *t1, *t2, *t3, *t4, *tval;
    int* tidx;
    cudaGetSymbolAddress((void**)&gi,      d_gi);
    cudaGetSymbolAddress((void**)&h0,      d_h0);
    cudaGetSymbolAddress((void**)&g,       d_g);
    cudaGetSymbolAddress((void**)&gn,      d_gn);
    cudaGetSymbolAddress((void**)&sim,     d_sim);
    cudaGetSymbolAddress((void**)&tidx,    d_tidx);
    cudaGetSymbolAddress((void**)&tval,    d_tval);
    cudaGetSymbolAddress((void**)&colsum,  d_colsum);
    cudaGetSymbolAddress((void**)&colZ,    d_colZ);
    cudaGetSymbolAddress((void**)&valid,   d_valid);
    cudaGetSymbolAddress((void**)&concept, d_concept);
    cudaGetSymbolAddress((void**)&cf,      d_cf);
    cudaGetSymbolAddress((void**)&cfn,     d_cfn);
    cudaGetSymbolAddress((void**)&hs,      d_hsb);
    cudaGetSymbolAddress((void**)&t1,      d_t1);
    cudaGetSymbolAddress((void**)&t2,      d_t2);
    cudaGetSymbolAddress((void**)&t3,      d_t3);
    cudaGetSymbolAddress((void**)&t4,      d_t4);

    cudaFuncSetAttribute((const void*)k_gru<true>,
                         cudaFuncAttributeMaxDynamicSharedMemorySize, 65536);
    cudaFuncSetAttribute((const void*)k_gru<false>,
                         cudaFuncAttributeMaxDynamicSharedMemorySize, 65536);

    const int MT = NS * TS;  // 262144

    // zero accumulators (consumed later)
    k_zero<<<(NS * HD + 255) / 256, 256>>>(concept, NS * HD);
    k_zero<<<(NS + 255) / 256, 256>>>(colsum, NS);
    k_zero<<<(NS + 255) / 256, 256>>>(colZ, NS);

    // gi0 = x @ Wih0^T + bih0   [262144, 384], K=32
    k_gemm<true, false><<<dim3(GD / 64, MT / 128, 1), 256>>>(
        x, Wih0, bih0, nullptr, gi, MT, GD, FI, FI);
    // GRU layer 0 (writes full sequence)
    k_gru<true><<<128, 384, 65536>>>(gi, Whh0, bhh0, h0);
    // gi1 = h0 @ Wih1^T + bih1   [262144, 384], K=128
    k_gemm<true, false><<<dim3(GD / 64, MT / 128, 1), 256>>>(
        h0, Wih1, bih1, nullptr, gi, MT, GD, HD, HD);
    // GRU layer 1 (writes final hidden only -> g)
    k_gru<false><<<128, 384, 65536>>>(gi, Whh1, bhh1, g);

    // normalized g, sim = gn @ gn^T
    k_rownorm<<<NS / 8, 256>>>(g, gn);
    k_gemm<true, false><<<dim3(NS / 64, NS / 128, 1), 256>>>(
        gn, gn, nullptr, nullptr, sim, NS, NS, HD, HD);

    // top-K selection + concept aggregation
    k_topk<<<NS, 256>>>(sim, tidx, tval, colsum);
    k_scatter<<<NS, 128>>>(tidx, tval, g, concept);
    k_diag_valid<<<NS, 128>>>(colsum, sim, g, concept, valid);

    // cf = lrelu(concept @ W_hc^T + b_hc) * valid
    k_gemm<true, true><<<dim3(HD / 64, NS / 128, 1), 256>>>(
        concept, W_hc, b_hc, valid, cf, NS, HD, HD, HD);
    k_rownorm<<<NS / 8, 256>>>(cf, cfn);

    // S = gn @ cfn^T ; attn = softmax over axis 0
    k_gemm<true, false><<<dim3(NS / 64, NS / 128, 1), 256>>>(
        gn, cfn, nullptr, nullptr, sim, NS, NS, HD, HD);
    k_colz<<<dim3(NS / 128, NS / 128), 128>>>(sim, colZ);
    k_scale<<<(int)(((size_t)NS * NS / 4) / 256), 256>>>(sim, colZ);

    // t1 = attn @ cf  (K=4096, split-K=8 into gi scratch, then reduce)
    k_gemm<false, false><<<dim3(HD / 64, NS / 128, 8), 256>>>(
        sim, cf, nullptr, nullptr, gi, NS, HD, NS, NS / 8);
    k_reduce<<<(NS * HD / 4 + 255) / 256, 256>>>(gi, t1, 8, NS * HD / 4);

    // hs = lrelu(t1 @ W_hs^T + b_hs)
    k_gemm<true, true><<<dim3(HD / 64, NS / 128, 1), 256>>>(
        t1, W_hs, b_hs, nullptr, hs, NS, HD, HD, HD);

    // back / fore / indi / pred
    k_gemm<true, true><<<dim3(HD / 64, NS / 128, 1), 256>>>(
        hs, W_back, b_back, nullptr, t1, NS, HD, HD, HD);
    k_gemm<true, true><<<dim3(HD / 64, NS / 128, 1), 256>>>(
        hs, W_fore, b_fore, nullptr, t2, NS, HD, HD, HD);
    k_sub<<<(NS * HD / 4) / 256, 256>>>(g, t1, t3);
    k_gemm<true, true><<<dim3(HD / 64, NS / 128, 1), 256>>>(
        t3, W_indi, b_indi, nullptr, t4, NS, HD, HD, HD);
    k_final<<<NS / 8, 256>>>(t2, t4, W_out, b_out, out);
}

// round 4
// speedup vs baseline: 1.0981x; 1.0300x over previous
#include <cuda_runtime.h>
#include <math.h>
#include <stdint.h>
#include <stddef.h>

// Problem dims (fixed by the dataset)
#define NS   4096      // batch
#define TS   64        // timesteps
#define FI   32        // input features
#define HD   128       // hidden
#define GD   384       // 3*H
#define NK   20        // top-k
#define SLOPE_F 0.2f

typedef unsigned long long ull;

// ---------------- f32x2 packed helpers (Blackwell FFMA2) --------------------
__device__ __forceinline__ ull pack2(float lo, float hi) {
    ull r;
    asm("mov.b64 %0, {%1, %2};" : "=l"(r) : "f"(lo), "f"(hi));
    return r;
}
__device__ __forceinline__ float2 unpack2(ull v) {
    float2 r;
    asm("mov.b64 {%0, %1}, %2;" : "=f"(r.x), "=f"(r.y) : "l"(v));
    return r;
}
__device__ __forceinline__ void ffma2(ull& d, ull a, ull b) {
    asm("fma.rn.f32x2 %0, %1, %2, %0;" : "+l"(d) : "l"(a), "l"(b));
}

// ---------------- scratch (device globals; no runtime allocation) ----------
__device__ float d_gi[(size_t)NS * TS * GD];     // gi0/gi1, later split-K scratch
__device__ float d_h0[(size_t)NS * TS * HD];     // layer0 hidden sequence
__device__ float d_g  [NS * HD];
__device__ float d_gn [NS * HD];
__device__ float d_sim[(size_t)NS * NS];         // sim, then S, then attn
__device__ int   d_tidx[NS * NK];
__device__ float d_tval[NS * NK];
__device__ float d_colsum[NS];
__device__ float d_colZ[NS];
__device__ float d_valid[NS];
__device__ float d_concept[NS * HD];
__device__ float d_cf [NS * HD];
__device__ float d_cfn[NS * HD];
__device__ float d_hsb[NS * HD];
__device__ float d_t1 [NS * HD];
__device__ float d_t2 [NS * HD];
__device__ float d_t3 [NS * HD];
__device__ float d_t4 [NS * HD];

// ---------------- fp32 GEMM: 128x64 tile, 256 thr, 8x4 micro, FFMA2 ---------
// A: [M,K] row-major. TRANSB: B is [N,K]; else B is [K,N].
// gridDim.z = number of K-splits; ksplit = K / gridDim.z (multiple of 16).
// When gridDim.z > 1: writes raw partials at C + z*M*N (bias/act applied later).
template<bool TRANSB, bool ACT>
__global__ __launch_bounds__(256) void k_gemm(
    const float* __restrict__ A, const float* __restrict__ B,
    const float* __restrict__ bias, const float* __restrict__ rs,
    float* __restrict__ C, int M, int N, int K, int ksplit)
{
    __shared__ alignas(16) float As[16][132];
    __shared__ alignas(16) float Bs[16][68];
    const int bm = blockIdx.y * 128, bn = blockIdx.x * 64;
    const int tid = threadIdx.x;
    const int kbase = blockIdx.z * ksplit;

    const int a_m = tid >> 1, a_k = (tid & 1) * 8;
    const int ty = tid >> 4, tx = tid & 15;
    const int m0 = ty * 8, n0 = tx * 4;

    // acc2[p][j]: packed pair (row m0+2p, row m0+2p+1) at column n0+j
    ull acc2[4][4];
    #pragma unroll
    for (int p = 0; p < 4; p++)
        #pragma unroll
        for (int j = 0; j < 4; j++) acc2[p][j] = 0ull;

    for (int k0 = kbase; k0 < kbase + ksplit; k0 += 16) {
        const float* Ap = A + (size_t)(bm + a_m) * K + k0 + a_k;
        float4 av0 = *(const float4*)(Ap);
        float4 av1 = *(const float4*)(Ap + 4);
        As[a_k + 0][a_m] = av0.x; As[a_k + 1][a_m] = av0.y;
        As[a_k + 2][a_m] = av0.z; As[a_k + 3][a_m] = av0.w;
        As[a_k + 4][a_m] = av1.x; As[a_k + 5][a_m] = av1.y;
        As[a_k + 6][a_m] = av1.z; As[a_k + 7][a_m] = av1.w;
        if (TRANSB) {
            const int b_n = tid >> 2, b_k = (tid & 3) * 4;
            float4 bv = *(const float4*)(B + (size_t)(bn + b_n) * K + k0 + b_k);
            Bs[b_k + 0][b_n] = bv.x; Bs[b_k + 1][b_n] = bv.y;
            Bs[b_k + 2][b_n] = bv.z; Bs[b_k + 3][b_n] = bv.w;
        } else {
            const int b_k = tid >> 4, b_n4 = (tid & 15) * 4;
            *(float4*)&Bs[b_k][b_n4] =
                *(const float4*)(B + (size_t)(k0 + b_k) * N + bn + b_n4);
        }
        __syncthreads();
        #pragma unroll
        for (int kk = 0; kk < 16; kk++) {
            // A rows m0..m0+7 as 4 packed pairs (consecutive m, direct reinterpret)
            ulonglong2 aP01 = *(const ulonglong2*)&As[kk][m0];
            ulonglong2 aP23 = *(const ulonglong2*)&As[kk][m0 + 4];
            float4 b = *(const float4*)&Bs[kk][n0];
            ull bd0 = pack2(b.x, b.x), bd1 = pack2(b.y, b.y);
            ull bd2 = pack2(b.z, b.z), bd3 = pack2(b.w, b.w);
            ffma2(acc2[0][0], aP01.x, bd0); ffma2(acc2[0][1], aP01.x, bd1);
            ffma2(acc2[0][2], aP01.x, bd2); ffma2(acc2[0][3], aP01.x, bd3);
            ffma2(acc2[1][0], aP01.y, bd0); ffma2(acc2[1][1], aP01.y, bd1);
            ffma2(acc2[1][2], aP01.y, bd2); ffma2(acc2[1][3], aP01.y, bd3);
            ffma2(acc2[2][0], aP23.x, bd0); ffma2(acc2[2][1], aP23.x, bd1);
            ffma2(acc2[2][2], aP23.x, bd2); ffma2(acc2[2][3], aP23.x, bd3);
            ffma2(acc2[3][0], aP23.y, bd0); ffma2(acc2[3][1], aP23.y, bd1);
            ffma2(acc2[3][2], aP23.y, bd2); ffma2(acc2[3][3], aP23.y, bd3);
        }
        __syncthreads();
    }

    float* Cw = C + (size_t)blockIdx.z * ((size_t)M * N);
    #pragma unroll
    for (int p = 0; p < 4; p++) {
        int rowA = bm + m0 + 2 * p;
        int rowB = rowA + 1;
        float rsA = rs ? rs[rowA] : 1.f;
        float rsB = rs ? rs[rowB] : 1.f;
        float va[4], vb[4];
        #pragma unroll
        for (int j = 0; j < 4; j++) {
            float2 v = unpack2(acc2[p][j]);
            float a = v.x, b = v.y;
            if (bias) { float bj = bias[bn + n0 + j]; a += bj; b += bj; }
            if (ACT) {
                a = a > 0.f ? a : SLOPE_F * a;
                b = b > 0.f ? b : SLOPE_F * b;
            }
            va[j] = a * rsA; vb[j] = b * rsB;
        }
        *(float4*)(Cw + (size_t)rowA * N + bn + n0) =
            make_float4(va[0], va[1], va[2], va[3]);
        *(float4*)(Cw + (size_t)rowB * N + bn + n0) =
            make_float4(vb[0], vb[1], vb[2], vb[3]);
    }
}

// reduce over split-K partial slices: C = sum_z P[z]
__global__ void k_reduce(const float* __restrict__ P, float* __restrict__ C,
                         int nslice, int total4)
{
    int i = blockIdx.x * blockDim.x + threadIdx.x;
    if (i >= total4) return;
    size_t b = (size_t)i * 4;
    float4 s = make_float4(0.f, 0.f, 0.f, 0.f);
    for (int z = 0; z < nslice; z++) {
        float4 v = *(const float4*)(P + (size_t)z * total4 * 4 + b);
        s.x += v.x; s.y += v.y; s.z += v.z; s.w += v.w;
    }
    *(float4*)(C + b) = s;
}

// ---------------- persistent GRU recurrent kernel (FFMA2) -------------------
// One CTA per 32 batch rows. 384 threads; thread o owns Whh row o in registers
// as 64 packed k-pairs. 4 packed accumulator chains (2 rows x 2).
template<bool WRITE_SEQ>
__global__ __launch_bounds__(384, 1) void k_gru(
    const float* __restrict__ gi, const float* __restrict__ Whh,
    const float* __restrict__ bhh, float* __restrict__ hout)
{
    extern __shared__ float sm[];
    float* h_sh  = sm;            // 32*128
    float* gh_sh = sm + 32 * HD;  // 32*384
    const int o = threadIdx.x;
    const int base = blockIdx.x * 32;

    ull wq[64];
    const ulonglong2* wg = (const ulonglong2*)(Whh + (size_t)o * HD);
    #pragma unroll
    for (int q = 0; q < 32; q++) {
        ulonglong2 t = wg[q];
        wq[2 * q] = t.x; wq[2 * q + 1] = t.y;
    }
    float bo = bhh[o];
    for (int idx = o; idx < 32 * HD; idx += GD) h_sh[idx] = 0.f;
    __syncthreads();

    for (int t = 0; t < TS; t++) {
        // gh[r,o] = h[r,:] . Whh[o,:]  — two rows per iter, 4 packed chains
        #pragma unroll 1
        for (int r = 0; r < 32; r += 2) {
            const ulonglong2* hA = (const ulonglong2*)(h_sh + r * HD);
            const ulonglong2* hB = (const ulonglong2*)(h_sh + (r + 1) * HD);
            ull a0 = 0ull, a1 = 0ull, b0 = 0ull, b1 = 0ull;
            #pragma unroll
            for (int q = 0; q < 32; q += 2) {
                ulonglong2 xA0 = hA[q], xA1 = hA[q + 1];
                ulonglong2 xB0 = hB[q], xB1 = hB[q + 1];
                ffma2(a0, xA0.x, wq[2 * q]);
                ffma2(a1, xA0.y, wq[2 * q + 1]);
                ffma2(b0, xB0.x, wq[2 * q]);
                ffma2(b1, xB0.y, wq[2 * q + 1]);
                ffma2(a0, xA1.x, wq[2 * q + 2]);
                ffma2(a1, xA1.y, wq[2 * q + 3]);
                ffma2(b0, xB1.x, wq[2 * q + 2]);
                ffma2(b1, xB1.y, wq[2 * q + 3]);
            }
            float2 pa0 = unpack2(a0), pa1 = unpack2(a1);
            float2 pb0 = unpack2(b0), pb1 = unpack2(b1);
            gh_sh[r * GD + o]       = ((pa0.x + pa0.y) + (pa1.x + pa1.y)) + bo;
            gh_sh[(r + 1) * GD + o] = ((pb0.x + pb0.y) + (pb1.x + pb1.y)) + bo;
        }
        __syncthreads();
        // gate update
        for (int idx = o; idx < 32 * HD; idx += GD) {
            int r = idx >> 7, j = idx & 127;
            size_t gib = ((size_t)(base + r) * TS + t) * GD;
            float gir = gi[gib + j];
            float giz = gi[gib + j + 128];
            float gin = gi[gib + j + 256];
            float ghr = gh_sh[r * GD + j];
            float ghz = gh_sh[r * GD + j + 128];
            float ghn = gh_sh[r * GD + j + 256];
            float rg = 1.f / (1.f + expf(-(gir + ghr)));
            float zg = 1.f / (1.f + expf(-(giz + ghz)));
            float ng = tanhf(gin + rg * ghn);
            float hprev = h_sh[idx];
            float hn = (1.f - zg) * ng + zg * hprev;
            h_sh[idx] = hn;
            if (WRITE_SEQ)
                hout[((size_t)(base + r) * TS + t) * HD + j] = hn;
            else if (t == TS - 1)
                hout[(size_t)(base + r) * HD + j] = hn;
        }
        __syncthreads();
    }
}

// ---------------- small helpers --------------------------------------------
__global__ void k_zero(float* p, int n) {
    int i = blockIdx.x * blockDim.x + threadIdx.x;
    if (i < n) p[i] = 0.f;
}

// row L2-normalize (128 floats/row), zero-norm rows -> zero
__global__ void k_rownorm(const float* __restrict__ src, float* __restrict__ dst) {
    int row = blockIdx.x * 8 + (threadIdx.x >> 5);
    int lane = threadIdx.x & 31;
    const float4* s4 = (const float4*)(src + (size_t)row * HD);
    float4 v = s4[lane];
    float ss = v.x*v.x + v.y*v.y + v.z*v.z + v.w*v.w;
    #pragma unroll
    for (int off = 16; off; off >>= 1) ss += __shfl_xor_sync(0xffffffffu, ss, off);
    float n = sqrtf(ss);
    float inv = (n > 0.f) ? 1.f / n : 0.f;
    ((float4*)(dst + (size_t)row * HD))[lane] =
        make_float4(v.x*inv, v.y*inv, v.z*inv, v.w*inv);
}

// top-K=20 per row of |sim| (diag excluded), jax-stable ties (lowest index).
__global__ __launch_bounds__(256) void k_topk(
    const float* __restrict__ sim, int* __restrict__ tidx,
    float* __restrict__ tval, float* __restrict__ colsum)
{
    int i = blockIdx.x;
    __shared__ float sabs[NS];
    __shared__ float wv[8];
    __shared__ int   wi[8];
    const float* row = sim + (size_t)i * NS;
    for (int c = threadIdx.x; c < NS; c += 256)
        sabs[c] = (c == i) ? -1.f : fabsf(row[c]);
    __syncthreads();
    for (int k = 0; k < NK; k++) {
        float bv = -2.f; int bi = 0;
        for (int c = threadIdx.x; c < NS; c += 256) {
            float v = sabs[c];
            if (v > bv) { bv = v; bi = c; }
        }
        #pragma unroll
        for (int off = 16; off; off >>= 1) {
            float ov = __shfl_down_sync(0xffffffffu, bv, off);
            int   oi = __shfl_down_sync(0xffffffffu, bi, off);
            if (ov > bv || (ov == bv && oi < bi)) { bv = ov; bi = oi; }
        }
        if ((threadIdx.x & 31) == 0) { wv[threadIdx.x >> 5] = bv; wi[threadIdx.x >> 5] = bi; }
        __syncthreads();
        if (threadIdx.x == 0) {
            for (int wd = 1; wd < 8; wd++)
                if (wv[wd] > bv || (wv[wd] == bv && wi[wd] < bi)) { bv = wv[wd]; bi = wi[wd]; }
            tidx[i * NK + k] = bi;
            float sv = row[bi];
            tval[i * NK + k] = sv;
            atomicAdd(&colsum[bi], sv);
            sabs[bi] = -2.f;
        }
        __syncthreads();
    }
}

// concept[c,:] += tval * g[i,:]  for each selected (i,c)
__global__ void k_scatter(const int* __restrict__ tidx, const float* __restrict__ tval,
                          const float* __restrict__ g, float* __restrict__ concept)
{
    int i = blockIdx.x, d = threadIdx.x;  // 128 threads
    float gv = g[(size_t)i * HD + d];
    #pragma unroll
    for (int k = 0; k < NK; k++) {
        int c = __ldg(&tidx[i * NK + k]);
        float v = __ldg(&tval[i * NK + k]);
        atomicAdd(&concept[(size_t)c * HD + d], v * gv);
    }
}

// add diag term where colsum!=0; compute valid[j] = (rowsum(concept[j]) != 0)
__global__ void k_diag_valid(const float* __restrict__ colsum, const float* __restrict__ sim,
                             const float* __restrict__ g, float* __restrict__ concept,
                             float* __restrict__ valid)
{
    int j = blockIdx.x, t = threadIdx.x;  // 128 threads
    float cs = colsum[j];
    float v = concept[(size_t)j * HD + t];
    if (cs != 0.f) {
        float dg = sim[(size_t)j * NS + j];
        v += dg * g[(size_t)j * HD + t];
        concept[(size_t)j * HD + t] = v;
    }
    float s = v;
    #pragma unroll
    for (int off = 16; off; off >>= 1) s += __shfl_xor_sync(0xffffffffu, s, off);
    __shared__ float ws[4];
    if ((t & 31) == 0) ws[t >> 5] = s;
    __syncthreads();
    if (t == 0) {
        float tot = ws[0] + ws[1] + ws[2] + ws[3];
        valid[j] = (tot != 0.f) ? 1.f : 0.f;
    }
}

// column sums of exp(S) (values bounded by 1, no max-shift needed)
__global__ void k_colz(const float* __restrict__ S, float* __restrict__ colZ) {
    int col = blockIdx.x * 128 + threadIdx.x;
    int r0 = blockIdx.y * 128;
    float s = 0.f;
    for (int r = r0; r < r0 + 128; r++) s += expf(S[(size_t)r * NS + col]);
    atomicAdd(&colZ[col], s);
}

// attn = exp(S) / colZ  (in place)
__global__ void k_scale(float* __restrict__ S, const float* __restrict__ colZ) {
    size_t q = (size_t)blockIdx.x * blockDim.x + threadIdx.x;  // float4 index
    size_t b = q * 4;
    float4 v = *(float4*)(S + b);
    int c = (int)(b & (NS - 1));
    float4 z = *(const float4*)(colZ + c);
    v.x = expf(v.x) / z.x; v.y = expf(v.y) / z.y;
    v.z = expf(v.z) / z.z; v.w = expf(v.w) / z.w;
    *(float4*)(S + b) = v;
}

__global__ void k_sub(const float* __restrict__ a, const float* __restrict__ b,
                      float* __restrict__ c) {
    size_t q = (size_t)blockIdx.x * blockDim.x + threadIdx.x;
    float4 av = *(const float4*)(a + q * 4);
    float4 bv = *(const float4*)(b + q * 4);
    *(float4*)(c + q * 4) = make_float4(av.x-bv.x, av.y-bv.y, av.z-bv.z, av.w-bv.w);
}

// pred[i] = (fore[i]+indi[i]) . W_out + b_out
__global__ void k_final(const float* __restrict__ fore, const float* __restrict__ indi,
                        const float* __restrict__ Wout, const float* __restrict__ bout,
                        float* __restrict__ out)
{
    int row = blockIdx.x * 8 + (threadIdx.x >> 5);
    int lane = threadIdx.x & 31;
    float4 a = ((const float4*)(fore + (size_t)row * HD))[lane];
    float4 b = ((const float4*)(indi + (size_t)row * HD))[lane];
    float4 w = ((const float4*)Wout)[lane];
    float s = (a.x+b.x)*w.x + (a.y+b.y)*w.y + (a.z+b.z)*w.z + (a.w+b.w)*w.w;
    #pragma unroll
    for (int off = 16; off; off >>= 1) s += __shfl_xor_sync(0xffffffffu, s, off);
    if (lane == 0) out[row] = s + bout[0];
}

// ---------------- driver -----------------------------------------------------
extern "C" void kernel_launch(void* const* d_in, const int* in_sizes, int n_in,
                              void* d_out, int out_size)
{
    const float* x     = (const float*)d_in[0];
    const float* Wih0  = (const float*)d_in[1];
    const float* Whh0  = (const float*)d_in[2];
    const float* bih0  = (const float*)d_in[3];
    const float* bhh0  = (const float*)d_in[4];
    const float* Wih1  = (const float*)d_in[5];
    const float* Whh1  = (const float*)d_in[6];
    const float* bih1  = (const float*)d_in[7];
    const float* bhh1  = (const float*)d_in[8];
    const float* W_hc  = (const float*)d_in[9];
    const float* b_hc  = (const float*)d_in[10];
    const float* W_hs  = (const float*)d_in[11];
    const float* b_hs  = (const float*)d_in[12];
    const float* W_fore= (const float*)d_in[13];
    const float* b_fore= (const float*)d_in[14];
    const float* W_back= (const float*)d_in[15];
    const float* b_back= (const float*)d_in[16];
    const float* W_indi= (const float*)d_in[17];
    const float* b_indi= (const float*)d_in[18];
    const float* W_out = (const float*)d_in[19];
    const float* b_out = (const float*)d_in[20];
    float* out = (float*)d_out;

    float *gi, *h0, *g, *gn, *sim, *colsum, *colZ, *valid, *concept;
    float *cf, *cfn, *hs, *t1, *t2, *t3, *t4, *tval;
    int* tidx;
    cudaGetSymbolAddress((void**)&gi,      d_gi);
    cudaGetSymbolAddress((void**)&h0,      d_h0);
    cudaGetSymbolAddress((void**)&g,       d_g);
    cudaGetSymbolAddress((void**)&gn,      d_gn);
    cudaGetSymbolAddress((void**)&sim,     d_sim);
    cudaGetSymbolAddress((void**)&tidx,    d_tidx);
    cudaGetSymbolAddress((void**)&tval,    d_tval);
    cudaGetSymbolAddress((void**)&colsum,  d_colsum);
    cudaGetSymbolAddress((void**)&colZ,    d_colZ);
    cudaGetSymbolAddress((void**)&valid,   d_valid);
    cudaGetSymbolAddress((void**)&concept, d_concept);
    cudaGetSymbolAddress((void**)&cf,      d_cf);
    cudaGetSymbolAddress((void**)&cfn,     d_cfn);
    cudaGetSymbolAddress((void**)&hs,      d_hsb);
    cudaGetSymbolAddress((void**)&t1,      d_t1);
    cudaGetSymbolAddress((void**)&t2,      d_t2);
    cudaGetSymbolAddress((void**)&t3,      d_t3);
    cudaGetSymbolAddress((void**)&t4,      d_t4);

    cudaFuncSetAttribute((const void*)k_gru<true>,
                         cudaFuncAttributeMaxDynamicSharedMemorySize, 65536);
    cudaFuncSetAttribute((const void*)k_gru<false>,
                         cudaFuncAttributeMaxDynamicSharedMemorySize, 65536);

    const int MT = NS * TS;  // 262144

    // zero accumulators (consumed later)
    k_zero<<<(NS * HD + 255) / 256, 256>>>(concept, NS * HD);
    k_zero<<<(NS + 255) / 256, 256>>>(colsum, NS);
    k_zero<<<(NS + 255) / 256, 256>>>(colZ, NS);

    // gi0 = x @ Wih0^T + bih0   [262144, 384], K=32
    k_gemm<true, false><<<dim3(GD / 64, MT / 128, 1), 256>>>(
        x, Wih0, bih0, nullptr, gi, MT, GD, FI, FI);
    // GRU layer 0 (writes full sequence)
    k_gru<true><<<128, 384, 65536>>>(gi, Whh0, bhh0, h0);
    // gi1 = h0 @ Wih1^T + bih1   [262144, 384], K=128
    k_gemm<true, false><<<dim3(GD / 64, MT / 128, 1), 256>>>(
        h0, Wih1, bih1, nullptr, gi, MT, GD, HD, HD);
    // GRU layer 1 (writes final hidden only -> g)
    k_gru<false><<<128, 384, 65536>>>(gi, Whh1, bhh1, g);

    // normalized g, sim = gn @ gn^T
    k_rownorm<<<NS / 8, 256>>>(g, gn);
    k_gemm<true, false><<<dim3(NS / 64, NS / 128, 1), 256>>>(
        gn, gn, nullptr, nullptr, sim, NS, NS, HD, HD);

    // top-K selection + concept aggregation
    k_topk<<<NS, 256>>>(sim, tidx, tval, colsum);
    k_scatter<<<NS, 128>>>(tidx, tval, g, concept);
    k_diag_valid<<<NS, 128>>>(colsum, sim, g, concept, valid);

    // cf = lrelu(concept @ W_hc^T + b_hc) * valid
    k_gemm<true, true><<<dim3(HD / 64, NS / 128, 1), 256>>>(
        concept, W_hc, b_hc, valid, cf, NS, HD, HD, HD);
    k_rownorm<<<NS / 8, 256>>>(cf, cfn);

    // S = gn @ cfn^T ; attn = softmax over axis 0
    k_gemm<true, false><<<dim3(NS / 64, NS / 128, 1), 256>>>(
        gn, cfn, nullptr, nullptr, sim, NS, NS, HD, HD);
    k_colz<<<dim3(NS / 128, NS / 128), 128>>>(sim, colZ);
    k_scale<<<(int)(((size_t)NS * NS / 4) / 256), 256>>>(sim, colZ);

    // t1 = attn @ cf  (K=4096, split-K=8 into gi scratch, then reduce)
    k_gemm<false, false><<<dim3(HD / 64, NS / 128, 8), 256>>>(
        sim, cf, nullptr, nullptr, gi, NS, HD, NS, NS / 8);
    k_reduce<<<(NS * HD / 4 + 255) / 256, 256>>>(gi, t1, 8, NS * HD / 4);

    // hs = lrelu(t1 @ W_hs^T + b_hs)
    k_gemm<true, true><<<dim3(HD / 64, NS / 128, 1), 256>>>(
        t1, W_hs, b_hs, nullptr, hs, NS, HD, HD, HD);

    // back / fore / indi / pred
    k_gemm<true, true><<<dim3(HD / 64, NS / 128, 1), 256>>>(
        hs, W_back, b_back, nullptr, t1, NS, HD, HD, HD);
    k_gemm<true, true><<<dim3(HD / 64, NS / 128, 1), 256>>>(
        hs, W_fore, b_fore, nullptr, t2, NS, HD, HD, HD);
    k_sub<<<(NS * HD / 4) / 256, 256>>>(g, t1, t3);
    k_gemm<true, true><<<dim3(HD / 64, NS / 128, 1), 256>>>(
        t3, W_indi, b_indi, nullptr, t4, NS, HD, HD, HD);
    k_final<<<NS / 8, 256>>>(t2, t4, W_out, b_out, out);
}

// round 5
// speedup vs baseline: 1.3572x; 1.2360x over previous
#include <cuda_runtime.h>
#include <math.h>
#include <stdint.h>
#include <stddef.h>

// Problem dims (fixed by the dataset)
#define NS   4096      // batch
#define TS   64        // timesteps
#define FI   32        // input features
#define HD   128       // hidden
#define GD   384       // 3*H
#define NK   20        // top-k
#define SLOPE_F 0.2f

typedef unsigned long long ull;

// ---------------- f32x2 packed helpers (Blackwell FFMA2) --------------------
__device__ __forceinline__ ull pack2(float lo, float hi) {
    ull r;
    asm("mov.b64 %0, {%1, %2};" : "=l"(r) : "f"(lo), "f"(hi));
    return r;
}
__device__ __forceinline__ float2 unpack2(ull v) {
    float2 r;
    asm("mov.b64 {%0, %1}, %2;" : "=f"(r.x), "=f"(r.y) : "l"(v));
    return r;
}
__device__ __forceinline__ void ffma2(ull& d, ull a, ull b) {
    asm("fma.rn.f32x2 %0, %1, %2, %0;" : "+l"(d) : "l"(a), "l"(b));
}

// ---------------- cp.async helpers -----------------------------------------
__device__ __forceinline__ void cp16(float* dst_sh, const float* src_g) {
    uint32_t d = (uint32_t)__cvta_generic_to_shared(dst_sh);
    asm volatile("cp.async.ca.shared.global [%0], [%1], 16;" :: "r"(d), "l"(src_g));
}
__device__ __forceinline__ void cp_commit() {
    asm volatile("cp.async.commit_group;");
}
__device__ __forceinline__ void cp_wait_all() {
    asm volatile("cp.async.wait_all;");
}

// ---------------- scratch (device globals; no runtime allocation) ----------
__device__ float d_gi[(size_t)NS * TS * GD];     // gi0/gi1, later split-K scratch
__device__ float d_h0[(size_t)NS * TS * HD];     // layer0 hidden sequence
__device__ float d_g  [NS * HD];
__device__ float d_gn [NS * HD];
__device__ float d_sim[(size_t)NS * NS];         // sim, then S, then attn
__device__ int   d_tidx[NS * NK];
__device__ float d_tval[NS * NK];
__device__ float d_colsum[NS];
__device__ float d_colZ[NS];
__device__ float d_valid[NS];
__device__ float d_concept[NS * HD];
__device__ float d_cf [NS * HD];
__device__ float d_cfn[NS * HD];
__device__ float d_hsb[NS * HD];
__device__ float d_t1 [NS * HD];
__device__ float d_t2 [NS * HD];
__device__ float d_t3 [NS * HD];
__device__ float d_t4 [NS * HD];

// ---------------- fp32 GEMM: 128x64 tile, 256 thr, 8x4 micro, FFMA2 ---------
template<bool TRANSB, bool ACT>
__global__ __launch_bounds__(256) void k_gemm(
    const float* __restrict__ A, const float* __restrict__ B,
    const float* __restrict__ bias, const float* __restrict__ rs,
    float* __restrict__ C, int M, int N, int K, int ksplit)
{
    __shared__ alignas(16) float As[16][132];
    __shared__ alignas(16) float Bs[16][68];
    const int bm = blockIdx.y * 128, bn = blockIdx.x * 64;
    const int tid = threadIdx.x;
    const int kbase = blockIdx.z * ksplit;

    const int a_m = tid >> 1, a_k = (tid & 1) * 8;
    const int ty = tid >> 4, tx = tid & 15;
    const int m0 = ty * 8, n0 = tx * 4;

    ull acc2[4][4];
    #pragma unroll
    for (int p = 0; p < 4; p++)
        #pragma unroll
        for (int j = 0; j < 4; j++) acc2[p][j] = 0ull;

    for (int k0 = kbase; k0 < kbase + ksplit; k0 += 16) {
        const float* Ap = A + (size_t)(bm + a_m) * K + k0 + a_k;
        float4 av0 = *(const float4*)(Ap);
        float4 av1 = *(const float4*)(Ap + 4);
        As[a_k + 0][a_m] = av0.x; As[a_k + 1][a_m] = av0.y;
        As[a_k + 2][a_m] = av0.z; As[a_k + 3][a_m] = av0.w;
        As[a_k + 4][a_m] = av1.x; As[a_k + 5][a_m] = av1.y;
        As[a_k + 6][a_m] = av1.z; As[a_k + 7][a_m] = av1.w;
        if (TRANSB) {
            const int b_n = tid >> 2, b_k = (tid & 3) * 4;
            float4 bv = *(const float4*)(B + (size_t)(bn + b_n) * K + k0 + b_k);
            Bs[b_k + 0][b_n] = bv.x; Bs[b_k + 1][b_n] = bv.y;
            Bs[b_k + 2][b_n] = bv.z; Bs[b_k + 3][b_n] = bv.w;
        } else {
            const int b_k = tid >> 4, b_n4 = (tid & 15) * 4;
            *(float4*)&Bs[b_k][b_n4] =
                *(const float4*)(B + (size_t)(k0 + b_k) * N + bn + b_n4);
        }
        __syncthreads();
        #pragma unroll
        for (int kk = 0; kk < 16; kk++) {
            ulonglong2 aP01 = *(const ulonglong2*)&As[kk][m0];
            ulonglong2 aP23 = *(const ulonglong2*)&As[kk][m0 + 4];
            float4 b = *(const float4*)&Bs[kk][n0];
            ull bd0 = pack2(b.x, b.x), bd1 = pack2(b.y, b.y);
            ull bd2 = pack2(b.z, b.z), bd3 = pack2(b.w, b.w);
            ffma2(acc2[0][0], aP01.x, bd0); ffma2(acc2[0][1], aP01.x, bd1);
            ffma2(acc2[0][2], aP01.x, bd2); ffma2(acc2[0][3], aP01.x, bd3);
            ffma2(acc2[1][0], aP01.y, bd0); ffma2(acc2[1][1], aP01.y, bd1);
            ffma2(acc2[1][2], aP01.y, bd2); ffma2(acc2[1][3], aP01.y, bd3);
            ffma2(acc2[2][0], aP23.x, bd0); ffma2(acc2[2][1], aP23.x, bd1);
            ffma2(acc2[2][2], aP23.x, bd2); ffma2(acc2[2][3], aP23.x, bd3);
            ffma2(acc2[3][0], aP23.y, bd0); ffma2(acc2[3][1], aP23.y, bd1);
            ffma2(acc2[3][2], aP23.y, bd2); ffma2(acc2[3][3], aP23.y, bd3);
        }
        __syncthreads();
    }

    float* Cw = C + (size_t)blockIdx.z * ((size_t)M * N);
    #pragma unroll
    for (int p = 0; p < 4; p++) {
        int rowA = bm + m0 + 2 * p;
        int rowB = rowA + 1;
        float rsA = rs ? rs[rowA] : 1.f;
        float rsB = rs ? rs[rowB] : 1.f;
        float va[4], vb[4];
        #pragma unroll
        for (int j = 0; j < 4; j++) {
            float2 v = unpack2(acc2[p][j]);
            float a = v.x, b = v.y;
            if (bias) { float bj = bias[bn + n0 + j]; a += bj; b += bj; }
            if (ACT) {
                a = a > 0.f ? a : SLOPE_F * a;
                b = b > 0.f ? b : SLOPE_F * b;
            }
            va[j] = a * rsA; vb[j] = b * rsB;
        }
        *(float4*)(Cw + (size_t)rowA * N + bn + n0) =
            make_float4(va[0], va[1], va[2], va[3]);
        *(float4*)(Cw + (size_t)rowB * N + bn + n0) =
            make_float4(vb[0], vb[1], vb[2], vb[3]);
    }
}

// reduce over split-K partial slices: C = sum_z P[z]
__global__ void k_reduce(const float* __restrict__ P, float* __restrict__ C,
                         int nslice, int total4)
{
    int i = blockIdx.x * blockDim.x + threadIdx.x;
    if (i >= total4) return;
    size_t b = (size_t)i * 4;
    float4 s = make_float4(0.f, 0.f, 0.f, 0.f);
    for (int z = 0; z < nslice; z++) {
        float4 v = *(const float4*)(P + (size_t)z * total4 * 4 + b);
        s.x += v.x; s.y += v.y; s.z += v.z; s.w += v.w;
    }
    *(float4*)(C + b) = s;
}

// ---------------- persistent GRU recurrent kernel (FFMA2, spill-free) -------
// One CTA per 32 batch rows. 384 threads; thread o owns Whh row o in registers
// as 64 packed k-pairs. One row at a time, 2 packed chains (low live set).
// gi tile for step t prefetched into SMEM via cp.async during matvec of step t.
template<bool WRITE_SEQ>
__global__ __launch_bounds__(384, 1) void k_gru(
    const float* __restrict__ gi, const float* __restrict__ Whh,
    const float* __restrict__ bhh, float* __restrict__ hout)
{
    extern __shared__ float sm[];
    float* h_sh  = sm;                       // 32*128
    float* gh_sh = sm + 32 * HD;             // 32*384
    float* gi_sh = sm + 32 * HD + 32 * GD;   // 32*384
    const int o = threadIdx.x;
    const int base = blockIdx.x * 32;

    ull wq[64];
    const ulonglong2* wg = (const ulonglong2*)(Whh + (size_t)o * HD);
    #pragma unroll
    for (int q = 0; q < 32; q++) {
        ulonglong2 tv = wg[q];
        wq[2 * q] = tv.x; wq[2 * q + 1] = tv.y;
    }
    float bo = bhh[o];
    for (int idx = o; idx < 32 * HD; idx += GD) h_sh[idx] = 0.f;

    // prefetch mapping: thread o -> row pr, float4 slots pc + 12*i
    const int pr = o / 12, pc = o % 12;
    const bool pact = (pc < 12) && (pr < 32);
    {
        const float* src = gi + ((size_t)(base + pr) * TS + 0) * GD;
        if (pact) {
            #pragma unroll
            for (int i = 0; i < 8; i++) {
                int f = pc + 12 * i;
                cp16(gi_sh + pr * GD + f * 4, src + f * 4);
            }
        }
        cp_commit();
    }
    __syncthreads();

    for (int t = 0; t < TS; t++) {
        // matvec: gh[r,o] = h[r,:] . Whh[o,:] (one row per iter, 2 chains)
        #pragma unroll 1
        for (int r = 0; r < 32; r++) {
            const ulonglong2* hA = (const ulonglong2*)(h_sh + r * HD);
            ull a0 = 0ull, a1 = 0ull;
            #pragma unroll
            for (int q = 0; q < 32; q += 2) {
                ulonglong2 x0 = hA[q], x1 = hA[q + 1];
                ffma2(a0, x0.x, wq[2 * q]);
                ffma2(a1, x0.y, wq[2 * q + 1]);
                ffma2(a0, x1.x, wq[2 * q + 2]);
                ffma2(a1, x1.y, wq[2 * q + 3]);
            }
            float2 p0 = unpack2(a0), p1 = unpack2(a1);
            gh_sh[r * GD + o] = ((p0.x + p0.y) + (p1.x + p1.y)) + bo;
        }
        cp_wait_all();
        __syncthreads();
        // gate update (reads gi_sh + gh_sh, writes h_sh)
        #pragma unroll 1
        for (int idx = o; idx < 32 * HD; idx += GD) {
            int r = idx >> 7, j = idx & 127;
            float gir = gi_sh[r * GD + j];
            float giz = gi_sh[r * GD + j + 128];
            float gin = gi_sh[r * GD + j + 256];
            float ghr = gh_sh[r * GD + j];
            float ghz = gh_sh[r * GD + j + 128];
            float ghn = gh_sh[r * GD + j + 256];
            float rg = __fdividef(1.f, 1.f + __expf(-(gir + ghr)));
            float zg = __fdividef(1.f, 1.f + __expf(-(giz + ghz)));
            float a2 = gin + rg * ghn;
            float ng = 1.f - __fdividef(2.f, __expf(2.f * a2) + 1.f);
            float hprev = h_sh[idx];
            float hn = (1.f - zg) * ng + zg * hprev;
            h_sh[idx] = hn;
            if (WRITE_SEQ)
                hout[((size_t)(base + r) * TS + t) * HD + j] = hn;
            else if (t == TS - 1)
                hout[(size_t)(base + r) * HD + j] = hn;
        }
        __syncthreads();
        // prefetch gi for t+1 (all gate reads of gi_sh completed at barrier)
        if (t + 1 < TS) {
            const float* src = gi + ((size_t)(base + pr) * TS + (t + 1)) * GD;
            if (pact) {
                #pragma unroll
                for (int i = 0; i < 8; i++) {
                    int f = pc + 12 * i;
                    cp16(gi_sh + pr * GD + f * 4, src + f * 4);
                }
            }
            cp_commit();
        }
    }
}

// ---------------- small helpers --------------------------------------------
__global__ void k_zero(float* p, int n) {
    int i = blockIdx.x * blockDim.x + threadIdx.x;
    if (i < n) p[i] = 0.f;
}

// row L2-normalize (128 floats/row), zero-norm rows -> zero
__global__ void k_rownorm(const float* __restrict__ src, float* __restrict__ dst) {
    int row = blockIdx.x * 8 + (threadIdx.x >> 5);
    int lane = threadIdx.x & 31;
    const float4* s4 = (const float4*)(src + (size_t)row * HD);
    float4 v = s4[lane];
    float ss = v.x*v.x + v.y*v.y + v.z*v.z + v.w*v.w;
    #pragma unroll
    for (int off = 16; off; off >>= 1) ss += __shfl_xor_sync(0xffffffffu, ss, off);
    float n = sqrtf(ss);
    float inv = (n > 0.f) ? 1.f / n : 0.f;
    ((float4*)(dst + (size_t)row * HD))[lane] =
        make_float4(v.x*inv, v.y*inv, v.z*inv, v.w*inv);
}

// top-K=20 per row of |sim| (diag excluded), jax-stable ties (lowest index).
__global__ __launch_bounds__(256) void k_topk(
    const float* __restrict__ sim, int* __restrict__ tidx,
    float* __restrict__ tval, float* __restrict__ colsum)
{
    int i = blockIdx.x;
    __shared__ float sabs[NS];
    __shared__ float wv[8];
    __shared__ int   wi[8];
    const float* row = sim + (size_t)i * NS;
    for (int c = threadIdx.x; c < NS; c += 256)
        sabs[c] = (c == i) ? -1.f : fabsf(row[c]);
    __syncthreads();
    for (int k = 0; k < NK; k++) {
        float bv = -2.f; int bi = 0;
        for (int c = threadIdx.x; c < NS; c += 256) {
            float v = sabs[c];
            if (v > bv) { bv = v; bi = c; }
        }
        #pragma unroll
        for (int off = 16; off; off >>= 1) {
            float ov = __shfl_down_sync(0xffffffffu, bv, off);
            int   oi = __shfl_down_sync(0xffffffffu, bi, off);
            if (ov > bv || (ov == bv && oi < bi)) { bv = ov; bi = oi; }
        }
        if ((threadIdx.x & 31) == 0) { wv[threadIdx.x >> 5] = bv; wi[threadIdx.x >> 5] = bi; }
        __syncthreads();
        if (threadIdx.x == 0) {
            for (int wd = 1; wd < 8; wd++)
                if (wv[wd] > bv || (wv[wd] == bv && wi[wd] < bi)) { bv = wv[wd]; bi = wi[wd]; }
            tidx[i * NK + k] = bi;
            float sv = row[bi];
            tval[i * NK + k] = sv;
            atomicAdd(&colsum[bi], sv);
            sabs[bi] = -2.f;
        }
        __syncthreads();
    }
}

// concept[c,:] += tval * g[i,:]  for each selected (i,c)
__global__ void k_scatter(const int* __restrict__ tidx, const float* __restrict__ tval,
                          const float* __restrict__ g, float* __restrict__ concept)
{
    int i = blockIdx.x, d = threadIdx.x;  // 128 threads
    float gv = g[(size_t)i * HD + d];
    #pragma unroll
    for (int k = 0; k < NK; k++) {
        int c = __ldg(&tidx[i * NK + k]);
        float v = __ldg(&tval[i * NK + k]);
        atomicAdd(&concept[(size_t)c * HD + d], v * gv);
    }
}

// add diag term where colsum!=0; compute valid[j] = (rowsum(concept[j]) != 0)
__global__ void k_diag_valid(const float* __restrict__ colsum, const float* __restrict__ sim,
                             const float* __restrict__ g, float* __restrict__ concept,
                             float* __restrict__ valid)
{
    int j = blockIdx.x, t = threadIdx.x;  // 128 threads
    float cs = colsum[j];
    float v = concept[(size_t)j * HD + t];
    if (cs != 0.f) {
        float dg = sim[(size_t)j * NS + j];
        v += dg * g[(size_t)j * HD + t];
        concept[(size_t)j * HD + t] = v;
    }
    float s = v;
    #pragma unroll
    for (int off = 16; off; off >>= 1) s += __shfl_xor_sync(0xffffffffu, s, off);
    __shared__ float ws[4];
    if ((t & 31) == 0) ws[t >> 5] = s;
    __syncthreads();
    if (t == 0) {
        float tot = ws[0] + ws[1] + ws[2] + ws[3];
        valid[j] = (tot != 0.f) ? 1.f : 0.f;
    }
}

// column sums of exp(S) (values bounded by 1, no max-shift needed)
__global__ void k_colz(const float* __restrict__ S, float* __restrict__ colZ) {
    int col = blockIdx.x * 128 + threadIdx.x;
    int r0 = blockIdx.y * 128;
    float s = 0.f;
    for (int r = r0; r < r0 + 128; r++) s += __expf(S[(size_t)r * NS + col]);
    atomicAdd(&colZ[col], s);
}

// colZ -> 1/colZ
__global__ void k_recip(float* __restrict__ colZ) {
    int i = blockIdx.x * blockDim.x + threadIdx.x;
    if (i < NS) colZ[i] = __fdividef(1.f, colZ[i]);
}

// attn = exp(S) * rcpZ  (in place)
__global__ void k_scale(float* __restrict__ S, const float* __restrict__ colZ) {
    size_t q = (size_t)blockIdx.x * blockDim.x + threadIdx.x;  // float4 index
    size_t b = q * 4;
    float4 v = *(float4*)(S + b);
    int c = (int)(b & (NS - 1));
    float4 z = *(const float4*)(colZ + c);
    v.x = __expf(v.x) * z.x; v.y = __expf(v.y) * z.y;
    v.z = __expf(v.z) * z.z; v.w = __expf(v.w) * z.w;
    *(float4*)(S + b) = v;
}

__global__ void k_sub(const float* __restrict__ a, const float* __restrict__ b,
                      float* __restrict__ c) {
    size_t q = (size_t)blockIdx.x * blockDim.x + threadIdx.x;
    float4 av = *(const float4*)(a + q * 4);
    float4 bv = *(const float4*)(b + q * 4);
    *(float4*)(c + q * 4) = make_float4(av.x-bv.x, av.y-bv.y, av.z-bv.z, av.w-bv.w);
}

// pred[i] = (fore[i]+indi[i]) . W_out + b_out
__global__ void k_final(const float* __restrict__ fore, const float* __restrict__ indi,
                        const float* __restrict__ Wout, const float* __restrict__ bout,
                        float* __restrict__ out)
{
    int row = blockIdx.x * 8 + (threadIdx.x >> 5);
    int lane = threadIdx.x & 31;
    float4 a = ((const float4*)(fore + (size_t)row * HD))[lane];
    float4 b = ((const float4*)(indi + (size_t)row * HD))[lane];
    float4 w = ((const float4*)Wout)[lane];
    float s = (a.x+b.x)*w.x + (a.y+b.y)*w.y + (a.z+b.z)*w.z + (a.w+b.w)*w.w;
    #pragma unroll
    for (int off = 16; off; off >>= 1) s += __shfl_xor_sync(0xffffffffu, s, off);
    if (lane == 0) out[row] = s + bout[0];
}

// ---------------- driver -----------------------------------------------------
extern "C" void kernel_launch(void* const* d_in, const int* in_sizes, int n_in,
                              void* d_out, int out_size)
{
    const float* x     = (const float*)d_in[0];
    const float* Wih0  = (const float*)d_in[1];
    const float* Whh0  = (const float*)d_in[2];
    const float* bih0  = (const float*)d_in[3];
    const float* bhh0  = (const float*)d_in[4];
    const float* Wih1  = (const float*)d_in[5];
    const float* Whh1  = (const float*)d_in[6];
    const float* bih1  = (const float*)d_in[7];
    const float* bhh1  = (const float*)d_in[8];
    const float* W_hc  = (const float*)d_in[9];
    const float* b_hc  = (const float*)d_in[10];
    const float* W_hs  = (const float*)d_in[11];
    const float* b_hs  = (const float*)d_in[12];
    const float* W_fore= (const float*)d_in[13];
    const float* b_fore= (const float*)d_in[14];
    const float* W_back= (const float*)d_in[15];
    const float* b_back= (const float*)d_in[16];
    const float* W_indi= (const float*)d_in[17];
    const float* b_indi= (const float*)d_in[18];
    const float* W_out = (const float*)d_in[19];
    const float* b_out = (const float*)d_in[20];
    float* out = (float*)d_out;

    float *gi, *h0, *g, *gn, *sim, *colsum, *colZ, *valid, *concept;
    float *cf, *cfn, *hs, *t1, *t2, *t3, *t4, *tval;
    int* tidx;
    cudaGetSymbolAddress((void**)&gi,      d_gi);
    cudaGetSymbolAddress((void**)&h0,      d_h0);
    cudaGetSymbolAddress((void**)&g,       d_g);
    cudaGetSymbolAddress((void**)&gn,      d_gn);
    cudaGetSymbolAddress((void**)&sim,     d_sim);
    cudaGetSymbolAddress((void**)&tidx,    d_tidx);
    cudaGetSymbolAddress((void**)&tval,    d_tval);
    cudaGetSymbolAddress((void**)&colsum,  d_colsum);
    cudaGetSymbolAddress((void**)&colZ,    d_colZ);
    cudaGetSymbolAddress((void**)&valid,   d_valid);
    cudaGetSymbolAddress((void**)&concept, d_concept);
    cudaGetSymbolAddress((void**)&cf,      d_cf);
    cudaGetSymbolAddress((void**)&cfn,     d_cfn);
    cudaGetSymbolAddress((void**)&hs,      d_hsb);
    cudaGetSymbolAddress((void**)&t1,      d_t1);
    cudaGetSymbolAddress((void**)&t2,      d_t2);
    cudaGetSymbolAddress((void**)&t3,      d_t3);
    cudaGetSymbolAddress((void**)&t4,      d_t4);

    const int GRU_SMEM = (32 * HD + 32 * GD + 32 * GD) * 4;  // 114688 B
    cudaFuncSetAttribute((const void*)k_gru<true>,
                         cudaFuncAttributeMaxDynamicSharedMemorySize, GRU_SMEM);
    cudaFuncSetAttribute((const void*)k_gru<false>,
                         cudaFuncAttributeMaxDynamicSharedMemorySize, GRU_SMEM);

    const int MT = NS * TS;  // 262144

    // zero accumulators (consumed later).
    // Launch order note: exactly 5 launches precede gru0 so ncu (-s 5 -c 1)
    // captures the GRU kernel.
    k_zero<<<(NS * HD + 255) / 256, 256>>>(concept, NS * HD);   // 1
    k_zero<<<(NS + 255) / 256, 256>>>(colsum, NS);              // 2
    k_zero<<<(NS + 255) / 256, 256>>>(colZ, NS);                // 3

    // gi0 = x @ Wih0^T + bih0   [262144, 384], K=32
    k_gemm<true, false><<<dim3(GD / 64, MT / 128, 1), 256>>>(   // 4
        x, Wih0, bih0, nullptr, gi, MT, GD, FI, FI);
    k_zero<<<(NS * NK + 255) / 256, 256>>>(tval, NS * NK);      // 5 (spacer; tval rewritten later)
    // GRU layer 0 (writes full sequence)                        // 6 <- ncu capture
    k_gru<true><<<128, 384, GRU_SMEM>>>(gi, Whh0, bhh0, h0);
    // gi1 = h0 @ Wih1^T + bih1   [262144, 384], K=128
    k_gemm<true, false><<<dim3(GD / 64, MT / 128, 1), 256>>>(
        h0, Wih1, bih1, nullptr, gi, MT, GD, HD, HD);
    // GRU layer 1 (writes final hidden only -> g)
    k_gru<false><<<128, 384, GRU_SMEM>>>(gi, Whh1, bhh1, g);

    // normalized g, sim = gn @ gn^T
    k_rownorm<<<NS / 8, 256>>>(g, gn);
    k_gemm<true, false><<<dim3(NS / 64, NS / 128, 1), 256>>>(
        gn, gn, nullptr, nullptr, sim, NS, NS, HD, HD);

    // top-K selection + concept aggregation
    k_topk<<<NS, 256>>>(sim, tidx, tval, colsum);
    k_scatter<<<NS, 128>>>(tidx, tval, g, concept);
    k_diag_valid<<<NS, 128>>>(colsum, sim, g, concept, valid);

    // cf = lrelu(concept @ W_hc^T + b_hc) * valid
    k_gemm<true, true><<<dim3(HD / 64, NS / 128, 1), 256>>>(
        concept, W_hc, b_hc, valid, cf, NS, HD, HD, HD);
    k_rownorm<<<NS / 8, 256>>>(cf, cfn);

    // S = gn @ cfn^T ; attn = softmax over axis 0
    k_gemm<true, false><<<dim3(NS / 64, NS / 128, 1), 256>>>(
        gn, cfn, nullptr, nullptr, sim, NS, NS, HD, HD);
    k_colz<<<dim3(NS / 128, NS / 128), 128>>>(sim, colZ);
    k_recip<<<NS / 256, 256>>>(colZ);
    k_scale<<<(int)(((size_t)NS * NS / 4) / 256), 256>>>(sim, colZ);

    // t1 = attn @ cf  (K=4096, split-K=8 into gi scratch, then reduce)
    k_gemm<false, false><<<dim3(HD / 64, NS / 128, 8), 256>>>(
        sim, cf, nullptr, nullptr, gi, NS, HD, NS, NS / 8);
    k_reduce<<<(NS * HD / 4 + 255) / 256, 256>>>(gi, t1, 8, NS * HD / 4);

    // hs = lrelu(t1 @ W_hs^T + b_hs)
    k_gemm<true, true><<<dim3(HD / 64, NS / 128, 1), 256>>>(
        t1, W_hs, b_hs, nullptr, hs, NS, HD, HD, HD);

    // back / fore / indi / pred
    k_gemm<true, true><<<dim3(HD / 64, NS / 128, 1), 256>>>(
        hs, W_back, b_back, nullptr, t1, NS, HD, HD, HD);
    k_gemm<true, true><<<dim3(HD / 64, NS / 128, 1), 256>>>(
        hs, W_fore, b_fore, nullptr, t2, NS, HD, HD, HD);
    k_sub<<<(NS * HD / 4) / 256, 256>>>(g, t1, t3);
    k_gemm<true, true><<<dim3(HD / 64, NS / 128, 1), 256>>>(
        t3, W_indi, b_indi, nullptr, t4, NS, HD, HD, HD);
    k_final<<<NS / 8, 256>>>(t2, t4, W_out, b_out, out);
}

// round 6
// speedup vs baseline: 1.4636x; 1.0784x over previous
#include <cuda_runtime.h>
#include <math.h>
#include <stdint.h>
#include <stddef.h>

// Problem dims (fixed by the dataset)
#define NS   4096      // batch
#define TS   64        // timesteps
#define FI   32        // input features
#define HD   128       // hidden
#define GD   384       // 3*H
#define NK   20        // top-k
#define SLOPE_F 0.2f
#define GRROWS 28      // batch rows per GRU CTA (147 CTAs -> all 148 SMs)

typedef unsigned long long ull;

// ---------------- f32x2 packed helpers (Blackwell FFMA2) --------------------
__device__ __forceinline__ ull pack2(float lo, float hi) {
    ull r;
    asm("mov.b64 %0, {%1, %2};" : "=l"(r) : "f"(lo), "f"(hi));
    return r;
}
__device__ __forceinline__ float2 unpack2(ull v) {
    float2 r;
    asm("mov.b64 {%0, %1}, %2;" : "=f"(r.x), "=f"(r.y) : "l"(v));
    return r;
}
__device__ __forceinline__ void ffma2(ull& d, ull a, ull b) {
    asm("fma.rn.f32x2 %0, %1, %2, %0;" : "+l"(d) : "l"(a), "l"(b));
}

// ---------------- cp.async helpers -----------------------------------------
__device__ __forceinline__ void cp16(float* dst_sh, const float* src_g) {
    uint32_t d = (uint32_t)__cvta_generic_to_shared(dst_sh);
    asm volatile("cp.async.ca.shared.global [%0], [%1], 16;" :: "r"(d), "l"(src_g));
}
__device__ __forceinline__ void cp_commit() {
    asm volatile("cp.async.commit_group;");
}
__device__ __forceinline__ void cp_wait_all() {
    asm volatile("cp.async.wait_all;");
}

// ---------------- scratch (device globals; no runtime allocation) ----------
__device__ float d_gi[(size_t)NS * TS * GD];
__device__ float d_h0[(size_t)NS * TS * HD];
__device__ float d_g  [NS * HD];
__device__ float d_gn [NS * HD];
__device__ float d_sim[(size_t)NS * NS];
__device__ int   d_tidx[NS * NK];
__device__ float d_tval[NS * NK];
__device__ float d_colsum[NS];
__device__ float d_colZ[NS];
__device__ float d_valid[NS];
__device__ float d_concept[NS * HD];
__device__ float d_cf [NS * HD];
__device__ float d_cfn[NS * HD];
__device__ float d_hsb[NS * HD];
__device__ float d_t1 [NS * HD];
__device__ float d_t2 [NS * HD];
__device__ float d_t3 [NS * HD];
__device__ float d_t4 [NS * HD];

// ---------------- fp32 GEMM: 128x64 tile, 256 thr, 8x4 micro, FFMA2 ---------
template<bool TRANSB, bool ACT>
__global__ __launch_bounds__(256) void k_gemm(
    const float* __restrict__ A, const float* __restrict__ B,
    const float* __restrict__ bias, const float* __restrict__ rs,
    float* __restrict__ C, int M, int N, int K, int ksplit)
{
    __shared__ alignas(16) float As[16][132];
    __shared__ alignas(16) float Bs[16][68];
    const int bm = blockIdx.y * 128, bn = blockIdx.x * 64;
    const int tid = threadIdx.x;
    const int kbase = blockIdx.z * ksplit;

    const int a_m = tid >> 1, a_k = (tid & 1) * 8;
    const int ty = tid >> 4, tx = tid & 15;
    const int m0 = ty * 8, n0 = tx * 4;

    ull acc2[4][4];
    #pragma unroll
    for (int p = 0; p < 4; p++)
        #pragma unroll
        for (int j = 0; j < 4; j++) acc2[p][j] = 0ull;

    for (int k0 = kbase; k0 < kbase + ksplit; k0 += 16) {
        const float* Ap = A + (size_t)(bm + a_m) * K + k0 + a_k;
        float4 av0 = *(const float4*)(Ap);
        float4 av1 = *(const float4*)(Ap + 4);
        As[a_k + 0][a_m] = av0.x; As[a_k + 1][a_m] = av0.y;
        As[a_k + 2][a_m] = av0.z; As[a_k + 3][a_m] = av0.w;
        As[a_k + 4][a_m] = av1.x; As[a_k + 5][a_m] = av1.y;
        As[a_k + 6][a_m] = av1.z; As[a_k + 7][a_m] = av1.w;
        if (TRANSB) {
            const int b_n = tid >> 2, b_k = (tid & 3) * 4;
            float4 bv = *(const float4*)(B + (size_t)(bn + b_n) * K + k0 + b_k);
            Bs[b_k + 0][b_n] = bv.x; Bs[b_k + 1][b_n] = bv.y;
            Bs[b_k + 2][b_n] = bv.z; Bs[b_k + 3][b_n] = bv.w;
        } else {
            const int b_k = tid >> 4, b_n4 = (tid & 15) * 4;
            *(float4*)&Bs[b_k][b_n4] =
                *(const float4*)(B + (size_t)(k0 + b_k) * N + bn + b_n4);
        }
        __syncthreads();
        #pragma unroll
        for (int kk = 0; kk < 16; kk++) {
            ulonglong2 aP01 = *(const ulonglong2*)&As[kk][m0];
            ulonglong2 aP23 = *(const ulonglong2*)&As[kk][m0 + 4];
            float4 b = *(const float4*)&Bs[kk][n0];
            ull bd0 = pack2(b.x, b.x), bd1 = pack2(b.y, b.y);
            ull bd2 = pack2(b.z, b.z), bd3 = pack2(b.w, b.w);
            ffma2(acc2[0][0], aP01.x, bd0); ffma2(acc2[0][1], aP01.x, bd1);
            ffma2(acc2[0][2], aP01.x, bd2); ffma2(acc2[0][3], aP01.x, bd3);
            ffma2(acc2[1][0], aP01.y, bd0); ffma2(acc2[1][1], aP01.y, bd1);
            ffma2(acc2[1][2], aP01.y, bd2); ffma2(acc2[1][3], aP01.y, bd3);
            ffma2(acc2[2][0], aP23.x, bd0); ffma2(acc2[2][1], aP23.x, bd1);
            ffma2(acc2[2][2], aP23.x, bd2); ffma2(acc2[2][3], aP23.x, bd3);
            ffma2(acc2[3][0], aP23.y, bd0); ffma2(acc2[3][1], aP23.y, bd1);
            ffma2(acc2[3][2], aP23.y, bd2); ffma2(acc2[3][3], aP23.y, bd3);
        }
        __syncthreads();
    }

    float* Cw = C + (size_t)blockIdx.z * ((size_t)M * N);
    #pragma unroll
    for (int p = 0; p < 4; p++) {
        int rowA = bm + m0 + 2 * p;
        int rowB = rowA + 1;
        float rsA = rs ? rs[rowA] : 1.f;
        float rsB = rs ? rs[rowB] : 1.f;
        float va[4], vb[4];
        #pragma unroll
        for (int j = 0; j < 4; j++) {
            float2 v = unpack2(acc2[p][j]);
            float a = v.x, b = v.y;
            if (bias) { float bj = bias[bn + n0 + j]; a += bj; b += bj; }
            if (ACT) {
                a = a > 0.f ? a : SLOPE_F * a;
                b = b > 0.f ? b : SLOPE_F * b;
            }
            va[j] = a * rsA; vb[j] = b * rsB;
        }
        *(float4*)(Cw + (size_t)rowA * N + bn + n0) =
            make_float4(va[0], va[1], va[2], va[3]);
        *(float4*)(Cw + (size_t)rowB * N + bn + n0) =
            make_float4(vb[0], vb[1], vb[2], vb[3]);
    }
}

// ---------------- fp32 GEMM: 64x64 tile (for NS x 128 x 128 head GEMMs) -----
// SUBPRE: C = pre - act(A@B^T + bias)   (fuses the g - back subtraction)
template<bool ACT, bool SUBPRE>
__global__ __launch_bounds__(256) void k_gemm64(
    const float* __restrict__ A, const float* __restrict__ B,
    const float* __restrict__ bias, const float* __restrict__ rs,
    const float* __restrict__ pre, float* __restrict__ C,
    int M, int N, int K)
{
    __shared__ alignas(16) float As[16][68];
    __shared__ alignas(16) float Bs[16][68];
    const int bm = blockIdx.y * 64, bn = blockIdx.x * 64;
    const int tid = threadIdx.x;
    const int a_m = tid >> 2, a_k = (tid & 3) * 4;
    const int ty = tid >> 4, tx = tid & 15;
    const int m0 = ty * 4, n0 = tx * 4;

    ull acc2[2][4];
    #pragma unroll
    for (int p = 0; p < 2; p++)
        #pragma unroll
        for (int j = 0; j < 4; j++) acc2[p][j] = 0ull;

    for (int k0 = 0; k0 < K; k0 += 16) {
        float4 av = *(const float4*)(A + (size_t)(bm + a_m) * K + k0 + a_k);
        As[a_k + 0][a_m] = av.x; As[a_k + 1][a_m] = av.y;
        As[a_k + 2][a_m] = av.z; As[a_k + 3][a_m] = av.w;
        float4 bv = *(const float4*)(B + (size_t)(bn + a_m) * K + k0 + a_k);
        Bs[a_k + 0][a_m] = bv.x; Bs[a_k + 1][a_m] = bv.y;
        Bs[a_k + 2][a_m] = bv.z; Bs[a_k + 3][a_m] = bv.w;
        __syncthreads();
        #pragma unroll
        for (int kk = 0; kk < 16; kk++) {
            ulonglong2 aP = *(const ulonglong2*)&As[kk][m0];
            float4 b = *(const float4*)&Bs[kk][n0];
            ull bd0 = pack2(b.x, b.x), bd1 = pack2(b.y, b.y);
            ull bd2 = pack2(b.z, b.z), bd3 = pack2(b.w, b.w);
            ffma2(acc2[0][0], aP.x, bd0); ffma2(acc2[0][1], aP.x, bd1);
            ffma2(acc2[0][2], aP.x, bd2); ffma2(acc2[0][3], aP.x, bd3);
            ffma2(acc2[1][0], aP.y, bd0); ffma2(acc2[1][1], aP.y, bd1);
            ffma2(acc2[1][2], aP.y, bd2); ffma2(acc2[1][3], aP.y, bd3);
        }
        __syncthreads();
    }

    #pragma unroll
    for (int p = 0; p < 2; p++) {
        int rowA = bm + m0 + 2 * p;
        int rowB = rowA + 1;
        float rsA = rs ? rs[rowA] : 1.f;
        float rsB = rs ? rs[rowB] : 1.f;
        float va[4], vb[4];
        #pragma unroll
        for (int j = 0; j < 4; j++) {
            float2 v = unpack2(acc2[p][j]);
            float a = v.x, b = v.y;
            if (bias) { float bj = bias[bn + n0 + j]; a += bj; b += bj; }
            if (ACT) {
                a = a > 0.f ? a : SLOPE_F * a;
                b = b > 0.f ? b : SLOPE_F * b;
            }
            a *= rsA; b *= rsB;
            if (SUBPRE) {
                a = pre[(size_t)rowA * N + bn + n0 + j] - a;
                b = pre[(size_t)rowB * N + bn + n0 + j] - b;
            }
            va[j] = a; vb[j] = b;
        }
        *(float4*)(C + (size_t)rowA * N + bn + n0) =
            make_float4(va[0], va[1], va[2], va[3]);
        *(float4*)(C + (size_t)rowB * N + bn + n0) =
            make_float4(vb[0], vb[1], vb[2], vb[3]);
    }
}

// reduce over split-K partial slices: C = sum_z P[z]
__global__ void k_reduce(const float* __restrict__ P, float* __restrict__ C,
                         int nslice, int total4)
{
    int i = blockIdx.x * blockDim.x + threadIdx.x;
    if (i >= total4) return;
    size_t b = (size_t)i * 4;
    float4 s = make_float4(0.f, 0.f, 0.f, 0.f);
    for (int z = 0; z < nslice; z++) {
        float4 v = *(const float4*)(P + (size_t)z * total4 * 4 + b);
        s.x += v.x; s.y += v.y; s.z += v.z; s.w += v.w;
    }
    *(float4*)(C + b) = s;
}

// ---------------- persistent GRU recurrent kernel (FFMA2, spill-free) -------
// One CTA per GRROWS batch rows (147 CTAs -> all SMs). 384 threads; thread o
// owns Whh row o in registers as 64 packed k-pairs. 2 packed chains per row.
// gi tile for step t+1 prefetched via cp.async during gate phase of step t.
template<bool WRITE_SEQ>
__global__ __launch_bounds__(384, 1) void k_gru(
    const float* __restrict__ gi, const float* __restrict__ Whh,
    const float* __restrict__ bhh, float* __restrict__ hout)
{
    extern __shared__ float sm[];
    float* h_sh  = sm;                            // GRROWS*128
    float* gh_sh = sm + GRROWS * HD;              // GRROWS*384
    float* gi_sh = sm + GRROWS * HD + GRROWS * GD;// GRROWS*384
    const int o = threadIdx.x;
    const int base = blockIdx.x * GRROWS;
    const int rows = (NS - base < GRROWS) ? (NS - base) : GRROWS;

    ull wq[64];
    const ulonglong2* wg = (const ulonglong2*)(Whh + (size_t)o * HD);
    #pragma unroll
    for (int q = 0; q < 32; q++) {
        ulonglong2 tv = wg[q];
        wq[2 * q] = tv.x; wq[2 * q + 1] = tv.y;
    }
    float bo = bhh[o];
    for (int idx = o; idx < rows * HD; idx += GD) h_sh[idx] = 0.f;

    // prefetch mapping: thread o -> row pr, float4 slots pc + 12*i
    const int pr = o / 12, pc = o % 12;
    const bool pact = (pr < rows);
    {
        const float* src = gi + ((size_t)(base + pr) * TS + 0) * GD;
        if (pact) {
            #pragma unroll
            for (int i = 0; i < 8; i++) {
                int f = pc + 12 * i;
                cp16(gi_sh + pr * GD + f * 4, src + f * 4);
            }
        }
        cp_commit();
    }
    __syncthreads();

    for (int t = 0; t < TS; t++) {
        // matvec: gh[r,o] = h[r,:] . Whh[o,:] (one row per iter, 2 chains)
        #pragma unroll 1
        for (int r = 0; r < rows; r++) {
            const ulonglong2* hA = (const ulonglong2*)(h_sh + r * HD);
            ull a0 = 0ull, a1 = 0ull;
            #pragma unroll
            for (int q = 0; q < 32; q += 2) {
                ulonglong2 x0 = hA[q], x1 = hA[q + 1];
                ffma2(a0, x0.x, wq[2 * q]);
                ffma2(a1, x0.y, wq[2 * q + 1]);
                ffma2(a0, x1.x, wq[2 * q + 2]);
                ffma2(a1, x1.y, wq[2 * q + 3]);
            }
            float2 p0 = unpack2(a0), p1 = unpack2(a1);
            gh_sh[r * GD + o] = ((p0.x + p0.y) + (p1.x + p1.y)) + bo;
        }
        cp_wait_all();
        __syncthreads();
        // gate update (reads gi_sh + gh_sh, writes h_sh)
        #pragma unroll 1
        for (int idx = o; idx < rows * HD; idx += GD) {
            int r = idx >> 7, j = idx & 127;
            float gir = gi_sh[r * GD + j];
            float giz = gi_sh[r * GD + j + 128];
            float gin = gi_sh[r * GD + j + 256];
            float ghr = gh_sh[r * GD + j];
            float ghz = gh_sh[r * GD + j + 128];
            float ghn = gh_sh[r * GD + j + 256];
            float rg = __fdividef(1.f, 1.f + __expf(-(gir + ghr)));
            float zg = __fdividef(1.f, 1.f + __expf(-(giz + ghz)));
            float a2 = gin + rg * ghn;
            float ng = 1.f - __fdividef(2.f, __expf(2.f * a2) + 1.f);
            float hprev = h_sh[idx];
            float hn = (1.f - zg) * ng + zg * hprev;
            h_sh[idx] = hn;
            if (WRITE_SEQ)
                hout[((size_t)(base + r) * TS + t) * HD + j] = hn;
            else if (t == TS - 1)
                hout[(size_t)(base + r) * HD + j] = hn;
        }
        __syncthreads();
        // prefetch gi for t+1 (all gate reads of gi_sh completed at barrier)
        if (t + 1 < TS) {
            const float* src = gi + ((size_t)(base + pr) * TS + (t + 1)) * GD;
            if (pact) {
                #pragma unroll
                for (int i = 0; i < 8; i++) {
                    int f = pc + 12 * i;
                    cp16(gi_sh + pr * GD + f * 4, src + f * 4);
                }
            }
            cp_commit();
        }
    }
}

// ---------------- small helpers --------------------------------------------
__global__ void k_zero(float* p, int n) {
    int i = blockIdx.x * blockDim.x + threadIdx.x;
    if (i < n) p[i] = 0.f;
}

__global__ void k_rownorm(const float* __restrict__ src, float* __restrict__ dst) {
    int row = blockIdx.x * 8 + (threadIdx.x >> 5);
    int lane = threadIdx.x & 31;
    const float4* s4 = (const float4*)(src + (size_t)row * HD);
    float4 v = s4[lane];
    float ss = v.x*v.x + v.y*v.y + v.z*v.z + v.w*v.w;
    #pragma unroll
    for (int off = 16; off; off >>= 1) ss += __shfl_xor_sync(0xffffffffu, ss, off);
    float n = sqrtf(ss);
    float inv = (n > 0.f) ? 1.f / n : 0.f;
    ((float4*)(dst + (size_t)row * HD))[lane] =
        make_float4(v.x*inv, v.y*inv, v.z*inv, v.w*inv);
}

// top-K=20 per row of |sim| (diag excluded), jax-stable ties (lowest index).
__global__ __launch_bounds__(256) void k_topk(
    const float* __restrict__ sim, int* __restrict__ tidx,
    float* __restrict__ tval, float* __restrict__ colsum)
{
    int i = blockIdx.x;
    __shared__ float sabs[NS];
    __shared__ float wv[8];
    __shared__ int   wi[8];
    const float* row = sim + (size_t)i * NS;
    for (int c = threadIdx.x; c < NS; c += 256)
        sabs[c] = (c == i) ? -1.f : fabsf(row[c]);
    __syncthreads();
    for (int k = 0; k < NK; k++) {
        float bv = -2.f; int bi = 0;
        for (int c = threadIdx.x; c < NS; c += 256) {
            float v = sabs[c];
            if (v > bv) { bv = v; bi = c; }
        }
        #pragma unroll
        for (int off = 16; off; off >>= 1) {
            float ov = __shfl_down_sync(0xffffffffu, bv, off);
            int   oi = __shfl_down_sync(0xffffffffu, bi, off);
            if (ov > bv || (ov == bv && oi < bi)) { bv = ov; bi = oi; }
        }
        if ((threadIdx.x & 31) == 0) { wv[threadIdx.x >> 5] = bv; wi[threadIdx.x >> 5] = bi; }
        __syncthreads();
        if (threadIdx.x == 0) {
            for (int wd = 1; wd < 8; wd++)
                if (wv[wd] > bv || (wv[wd] == bv && wi[wd] < bi)) { bv = wv[wd]; bi = wi[wd]; }
            tidx[i * NK + k] = bi;
            float sv = row[bi];
            tval[i * NK + k] = sv;
            atomicAdd(&colsum[bi], sv);
            sabs[bi] = -2.f;
        }
        __syncthreads();
    }
}

__global__ void k_scatter(const int* __restrict__ tidx, const float* __restrict__ tval,
                          const float* __restrict__ g, float* __restrict__ concept)
{
    int i = blockIdx.x, d = threadIdx.x;
    float gv = g[(size_t)i * HD + d];
    #pragma unroll
    for (int k = 0; k < NK; k++) {
        int c = __ldg(&tidx[i * NK + k]);
        float v = __ldg(&tval[i * NK + k]);
        atomicAdd(&concept[(size_t)c * HD + d], v * gv);
    }
}

__global__ void k_diag_valid(const float* __restrict__ colsum, const float* __restrict__ sim,
                             const float* __restrict__ g, float* __restrict__ concept,
                             float* __restrict__ valid)
{
    int j = blockIdx.x, t = threadIdx.x;
    float cs = colsum[j];
    float v = concept[(size_t)j * HD + t];
    if (cs != 0.f) {
        float dg = sim[(size_t)j * NS + j];
        v += dg * g[(size_t)j * HD + t];
        concept[(size_t)j * HD + t] = v;
    }
    float s = v;
    #pragma unroll
    for (int off = 16; off; off >>= 1) s += __shfl_xor_sync(0xffffffffu, s, off);
    __shared__ float ws[4];
    if ((t & 31) == 0) ws[t >> 5] = s;
    __syncthreads();
    if (t == 0) {
        float tot = ws[0] + ws[1] + ws[2] + ws[3];
        valid[j] = (tot != 0.f) ? 1.f : 0.f;
    }
}

__global__ void k_colz(const float* __restrict__ S, float* __restrict__ colZ) {
    int col = blockIdx.x * 128 + threadIdx.x;
    int r0 = blockIdx.y * 128;
    float s = 0.f;
    for (int r = r0; r < r0 + 128; r++) s += __expf(S[(size_t)r * NS + col]);
    atomicAdd(&colZ[col], s);
}

__global__ void k_recip(float* __restrict__ colZ) {
    int i = blockIdx.x * blockDim.x + threadIdx.x;
    if (i < NS) colZ[i] = __fdividef(1.f, colZ[i]);
}

__global__ void k_scale(float* __restrict__ S, const float* __restrict__ colZ) {
    size_t q = (size_t)blockIdx.x * blockDim.x + threadIdx.x;
    size_t b = q * 4;
    float4 v = *(float4*)(S + b);
    int c = (int)(b & (NS - 1));
    float4 z = *(const float4*)(colZ + c);
    v.x = __expf(v.x) * z.x; v.y = __expf(v.y) * z.y;
    v.z = __expf(v.z) * z.z; v.w = __expf(v.w) * z.w;
    *(float4*)(S + b) = v;
}

__global__ void k_final(const float* __restrict__ fore, const float* __restrict__ indi,
                        const float* __restrict__ Wout, const float* __restrict__ bout,
                        float* __restrict__ out)
{
    int row = blockIdx.x * 8 + (threadIdx.x >> 5);
    int lane = threadIdx.x & 31;
    float4 a = ((const float4*)(fore + (size_t)row * HD))[lane];
    float4 b = ((const float4*)(indi + (size_t)row * HD))[lane];
    float4 w = ((const float4*)Wout)[lane];
    float s = (a.x+b.x)*w.x + (a.y+b.y)*w.y + (a.z+b.z)*w.z + (a.w+b.w)*w.w;
    #pragma unroll
    for (int off = 16; off; off >>= 1) s += __shfl_xor_sync(0xffffffffu, s, off);
    if (lane == 0) out[row] = s + bout[0];
}

// ---------------- driver -----------------------------------------------------
extern "C" void kernel_launch(void* const* d_in, const int* in_sizes, int n_in,
                              void* d_out, int out_size)
{
    const float* x     = (const float*)d_in[0];
    const float* Wih0  = (const float*)d_in[1];
    const float* Whh0  = (const float*)d_in[2];
    const float* bih0  = (const float*)d_in[3];
    const float* bhh0  = (const float*)d_in[4];
    const float* Wih1  = (const float*)d_in[5];
    const float* Whh1  = (const float*)d_in[6];
    const float* bih1  = (const float*)d_in[7];
    const float* bhh1  = (const float*)d_in[8];
    const float* W_hc  = (const float*)d_in[9];
    const float* b_hc  = (const float*)d_in[10];
    const float* W_hs  = (const float*)d_in[11];
    const float* b_hs  = (const float*)d_in[12];
    const float* W_fore= (const float*)d_in[13];
    const float* b_fore= (const float*)d_in[14];
    const float* W_back= (const float*)d_in[15];
    const float* b_back= (const float*)d_in[16];
    const float* W_indi= (const float*)d_in[17];
    const float* b_indi= (const float*)d_in[18];
    const float* W_out = (const float*)d_in[19];
    const float* b_out = (const float*)d_in[20];
    float* out = (float*)d_out;

    float *gi, *h0, *g, *gn, *sim, *colsum, *colZ, *valid, *concept;
    float *cf, *cfn, *hs, *t1, *t2, *t3, *t4, *tval;
    int* tidx;
    cudaGetSymbolAddress((void**)&gi,      d_gi);
    cudaGetSymbolAddress((void**)&h0,      d_h0);
    cudaGetSymbolAddress((void**)&g,       d_g);
    cudaGetSymbolAddress((void**)&gn,      d_gn);
    cudaGetSymbolAddress((void**)&sim,     d_sim);
    cudaGetSymbolAddress((void**)&tidx,    d_tidx);
    cudaGetSymbolAddress((void**)&tval,    d_tval);
    cudaGetSymbolAddress((void**)&colsum,  d_colsum);
    cudaGetSymbolAddress((void**)&colZ,    d_colZ);
    cudaGetSymbolAddress((void**)&valid,   d_valid);
    cudaGetSymbolAddress((void**)&concept, d_concept);
    cudaGetSymbolAddress((void**)&cf,      d_cf);
    cudaGetSymbolAddress((void**)&cfn,     d_cfn);
    cudaGetSymbolAddress((void**)&hs,      d_hsb);
    cudaGetSymbolAddress((void**)&t1,      d_t1);
    cudaGetSymbolAddress((void**)&t2,      d_t2);
    cudaGetSymbolAddress((void**)&t3,      d_t3);
    cudaGetSymbolAddress((void**)&t4,      d_t4);

    const int GRU_SMEM = (GRROWS * HD + 2 * GRROWS * GD) * 4;  // 100352 B
    cudaFuncSetAttribute((const void*)k_gru<true>,
                         cudaFuncAttributeMaxDynamicSharedMemorySize, GRU_SMEM);
    cudaFuncSetAttribute((const void*)k_gru<false>,
                         cudaFuncAttributeMaxDynamicSharedMemorySize, GRU_SMEM);

    const int MT = NS * TS;         // 262144
    const int GRU_GRID = (NS + GRROWS - 1) / GRROWS;  // 147

    // Launch order: gru0 is our 4th launch so ncu (-s 5 -c 1, one harness
    // pre-launch) captures the GRU kernel.
    // #1 gi0 = x @ Wih0^T + bih0
    k_gemm<true, false><<<dim3(GD / 64, MT / 128, 1), 256>>>(
        x, Wih0, bih0, nullptr, gi, MT, GD, FI, FI);
    // #2, #3 tiny zeros (needed later)
    k_zero<<<(NS + 255) / 256, 256>>>(colsum, NS);
    k_zero<<<(NS + 255) / 256, 256>>>(colZ, NS);
    // #4 GRU layer 0 (writes full sequence)  <- ncu capture target
    k_gru<true><<<GRU_GRID, 384, GRU_SMEM>>>(gi, Whh0, bhh0, h0);
    // gi1 = h0 @ Wih1^T + bih1
    k_gemm<true, false><<<dim3(GD / 64, MT / 128, 1), 256>>>(
        h0, Wih1, bih1, nullptr, gi, MT, GD, HD, HD);
    // GRU layer 1 (writes final hidden only -> g)
    k_gru<false><<<GRU_GRID, 384, GRU_SMEM>>>(gi, Whh1, bhh1, g);

    // concept accumulator zero (before scatter)
    k_zero<<<(NS * HD + 255) / 256, 256>>>(concept, NS * HD);

    // normalized g, sim = gn @ gn^T
    k_rownorm<<<NS / 8, 256>>>(g, gn);
    k_gemm<true, false><<<dim3(NS / 64, NS / 128, 1), 256>>>(
        gn, gn, nullptr, nullptr, sim, NS, NS, HD, HD);

    // top-K selection + concept aggregation
    k_topk<<<NS, 256>>>(sim, tidx, tval, colsum);
    k_scatter<<<NS, 128>>>(tidx, tval, g, concept);
    k_diag_valid<<<NS, 128>>>(colsum, sim, g, concept, valid);

    // cf = lrelu(concept @ W_hc^T + b_hc) * valid
    k_gemm64<true, false><<<dim3(HD / 64, NS / 64), 256>>>(
        concept, W_hc, b_hc, valid, nullptr, cf, NS, HD, HD);
    k_rownorm<<<NS / 8, 256>>>(cf, cfn);

    // S = gn @ cfn^T ; attn = softmax over axis 0
    k_gemm<true, false><<<dim3(NS / 64, NS / 128, 1), 256>>>(
        gn, cfn, nullptr, nullptr, sim, NS, NS, HD, HD);
    k_colz<<<dim3(NS / 128, NS / 128), 128>>>(sim, colZ);
    k_recip<<<NS / 256, 256>>>(colZ);
    k_scale<<<(int)(((size_t)NS * NS / 4) / 256), 256>>>(sim, colZ);

    // t1 = attn @ cf  (K=4096, split-K=8 into gi scratch, then reduce)
    k_gemm<false, false><<<dim3(HD / 64, NS / 128, 8), 256>>>(
        sim, cf, nullptr, nullptr, gi, NS, HD, NS, NS / 8);
    k_reduce<<<(NS * HD / 4 + 255) / 256, 256>>>(gi, t1, 8, NS * HD / 4);

    // hs = lrelu(t1 @ W_hs^T + b_hs)
    k_gemm64<true, false><<<dim3(HD / 64, NS / 64), 256>>>(
        t1, W_hs, b_hs, nullptr, nullptr, hs, NS, HD, HD);

    // t3 = g - lrelu(hs @ W_back^T + b_back)   (fused subtract)
    k_gemm64<true, true><<<dim3(HD / 64, NS / 64), 256>>>(
        hs, W_back, b_back, nullptr, g, t3, NS, HD, HD);
    // t2 = lrelu(hs @ W_fore^T + b_fore)
    k_gemm64<true, false><<<dim3(HD / 64, NS / 64), 256>>>(
        hs, W_fore, b_fore, nullptr, nullptr, t2, NS, HD, HD);
    // t4 = lrelu(t3 @ W_indi^T + b_indi)
    k_gemm64<true, false><<<dim3(HD / 64, NS / 64), 256>>>(
        t3, W_indi, b_indi, nullptr, nullptr, t4, NS, HD, HD);
    k_final<<<NS / 8, 256>>>(t2, t4, W_out, b_out, out);
}